// round 1
// baseline (speedup 1.0000x reference)
#include <cuda_runtime.h>

// Problem constants
constexpr int Bc = 4;
constexpr int Ss = 2048;
constexpr int Dd = 1024;
constexpr int Hh = 16;
constexpr int HD = 64;
constexpr int Mtot = Bc * Ss;          // 8192 rows of x / o

// Scratch (device globals: no allocation allowed)
__device__ float g_q[(size_t)Bc * Hh * Ss * HD];   // [B,H,S,HD]
__device__ float g_k[(size_t)Bc * Hh * Ss * HD];
__device__ float g_v[(size_t)Bc * Hh * Ss * HD];
__device__ float g_o[(size_t)Mtot * Dd];           // [B,S,D] heads concatenated

// ---------------------------------------------------------------------------
// QKV projection GEMM: Y[m, n] = x[m, :] @ W[:, n] + bias
// M=8192, N=3072 (q|k|v, each 1024 = 16 heads x 64), K=1024
// 128x128 tile, BK=8, 256 threads, 8x8 per-thread micro-tile.
// ---------------------------------------------------------------------------
__global__ __launch_bounds__(256) void qkv_gemm(
    const float* __restrict__ x,
    const float* __restrict__ Wq, const float* __restrict__ Wk, const float* __restrict__ Wv,
    const float* __restrict__ bq, const float* __restrict__ bk, const float* __restrict__ bv)
{
    __shared__ float As[8][132];   // [k][m] transposed, padded
    __shared__ float Bs[8][128];   // [k][n]

    const int m0 = blockIdx.y * 128;
    const int n0 = blockIdx.x * 128;          // 0..3071, never crosses a q/k/v part
    const int part = n0 >> 10;                // 0=q, 1=k, 2=v
    const float* W    = (part == 0) ? Wq : (part == 1) ? Wk : Wv;
    const float* bias = (part == 0) ? bq : (part == 1) ? bk : bv;
    float* dst        = (part == 0) ? g_q : (part == 1) ? g_k : g_v;
    const int nn0 = n0 & 1023;                // column within the part

    const int tid = threadIdx.x;
    const int ar = tid >> 1;                  // A row 0..127
    const int ak = (tid & 1) * 4;             // A k-offset 0 or 4
    const int brow = tid >> 5;                // B k-row 0..7
    const int bc = (tid & 31) * 4;            // B col 0..124 (float4, same head)
    const int bh = (nn0 + bc) >> 6;           // head for this thread's B load
    const int be = (nn0 + bc) & 63;           // elem within head

    const int ty = tid >> 4, tx = tid & 15;

    float acc[8][8];
    #pragma unroll
    for (int i = 0; i < 8; i++)
        #pragma unroll
        for (int j = 0; j < 8; j++) acc[i][j] = 0.f;

    for (int k0 = 0; k0 < Dd; k0 += 8) {
        float4 a = *(const float4*)&x[(size_t)(m0 + ar) * Dd + k0 + ak];
        // W layout: [H, D, HD] -> element (d, (h,e)) at h*D*HD + d*HD + e
        float4 b = *(const float4*)&W[((size_t)bh * Dd + (k0 + brow)) * HD + be];
        __syncthreads();
        As[ak + 0][ar] = a.x; As[ak + 1][ar] = a.y;
        As[ak + 2][ar] = a.z; As[ak + 3][ar] = a.w;
        *(float4*)&Bs[brow][bc] = b;
        __syncthreads();
        #pragma unroll
        for (int k = 0; k < 8; k++) {
            float af[8], bf[8];
            *(float4*)&af[0] = *(const float4*)&As[k][ty * 8];
            *(float4*)&af[4] = *(const float4*)&As[k][ty * 8 + 4];
            *(float4*)&bf[0] = *(const float4*)&Bs[k][tx * 8];
            *(float4*)&bf[4] = *(const float4*)&Bs[k][tx * 8 + 4];
            #pragma unroll
            for (int i = 0; i < 8; i++)
                #pragma unroll
                for (int j = 0; j < 8; j++)
                    acc[i][j] = fmaf(af[i], bf[j], acc[i][j]);
        }
    }

    // Epilogue: + bias, scatter into [B,H,S,HD]
    #pragma unroll
    for (int i = 0; i < 8; i++) {
        const int m = m0 + ty * 8 + i;
        const int bidx = m >> 11;             // /2048
        const int s = m & 2047;
        #pragma unroll
        for (int j = 0; j < 8; j++) {
            const int nn = nn0 + tx * 8 + j;
            const int h = nn >> 6, e = nn & 63;
            dst[(((size_t)bidx * Hh + h) * Ss + s) * HD + e] = acc[i][j] + bias[nn];
        }
    }
}

// ---------------------------------------------------------------------------
// Output projection GEMM: out = g_o @ Wp + bp
// M=8192, N=1024, K=1024. Same skeleton.
// ---------------------------------------------------------------------------
__global__ __launch_bounds__(256) void proj_gemm(
    const float* __restrict__ Wp, const float* __restrict__ bp,
    float* __restrict__ out)
{
    __shared__ float As[8][132];
    __shared__ float Bs[8][128];

    const int m0 = blockIdx.y * 128;
    const int n0 = blockIdx.x * 128;

    const int tid = threadIdx.x;
    const int ar = tid >> 1;
    const int ak = (tid & 1) * 4;
    const int brow = tid >> 5;
    const int bc = (tid & 31) * 4;

    const int ty = tid >> 4, tx = tid & 15;

    float acc[8][8];
    #pragma unroll
    for (int i = 0; i < 8; i++)
        #pragma unroll
        for (int j = 0; j < 8; j++) acc[i][j] = 0.f;

    for (int k0 = 0; k0 < Dd; k0 += 8) {
        float4 a = *(const float4*)&g_o[(size_t)(m0 + ar) * Dd + k0 + ak];
        float4 b = *(const float4*)&Wp[(size_t)(k0 + brow) * Dd + n0 + bc];
        __syncthreads();
        As[ak + 0][ar] = a.x; As[ak + 1][ar] = a.y;
        As[ak + 2][ar] = a.z; As[ak + 3][ar] = a.w;
        *(float4*)&Bs[brow][bc] = b;
        __syncthreads();
        #pragma unroll
        for (int k = 0; k < 8; k++) {
            float af[8], bf[8];
            *(float4*)&af[0] = *(const float4*)&As[k][ty * 8];
            *(float4*)&af[4] = *(const float4*)&As[k][ty * 8 + 4];
            *(float4*)&bf[0] = *(const float4*)&Bs[k][tx * 8];
            *(float4*)&bf[4] = *(const float4*)&Bs[k][tx * 8 + 4];
            #pragma unroll
            for (int i = 0; i < 8; i++)
                #pragma unroll
                for (int j = 0; j < 8; j++)
                    acc[i][j] = fmaf(af[i], bf[j], acc[i][j]);
        }
    }

    #pragma unroll
    for (int i = 0; i < 8; i++) {
        const int m = m0 + ty * 8 + i;
        #pragma unroll
        for (int j = 0; j < 8; j++) {
            const int n = n0 + tx * 8 + j;
            out[(size_t)m * Dd + n] = acc[i][j] + bp[n];
        }
    }
}

// ---------------------------------------------------------------------------
// Causal flash attention: per (b,h) and 64-query tile, stream 64-key tiles.
// 64 threads (8x8 grid), 8x8 micro-tiles for QK^T and PV.
// Online softmax with 8-lane shfl row reductions.
// ---------------------------------------------------------------------------
constexpr int ATT_LD = 68;                               // padded row stride
constexpr int ATT_SMEM = 4 * 64 * ATT_LD * 4;            // 69632 bytes

__global__ __launch_bounds__(64) void attn_kernel()
{
    extern __shared__ float sm[];
    float* Qs = sm;                     // [e][r], stride ATT_LD
    float* Ks = sm + 64 * ATT_LD;       // [e][c]
    float* Vs = sm + 2 * 64 * ATT_LD;   // [c][e]
    float* Ps = sm + 3 * 64 * ATT_LD;   // [j][r]   (P transposed)

    const int bhid = blockIdx.y;                        // 0..63 = b*16+h
    const int qi = (int)gridDim.x - 1 - (int)blockIdx.x; // heavy tiles first
    const int q0 = qi * 64;

    const float* qb = g_q + (size_t)bhid * Ss * HD;
    const float* kb = g_k + (size_t)bhid * Ss * HD;
    const float* vb = g_v + (size_t)bhid * Ss * HD;

    const int t = threadIdx.x;
    const int ty = t >> 3, tx = t & 7;

    // Load Q tile (64 rows x 64 dims), transposed into Qs[e][r]
    #pragma unroll
    for (int i = 0; i < 16; i++) {
        const int f = i * 64 + t;
        const int row = f >> 4;
        const int e4 = (f & 15) * 4;
        float4 qv = *(const float4*)&qb[(size_t)(q0 + row) * HD + e4];
        Qs[(e4 + 0) * ATT_LD + row] = qv.x;
        Qs[(e4 + 1) * ATT_LD + row] = qv.y;
        Qs[(e4 + 2) * ATT_LD + row] = qv.z;
        Qs[(e4 + 3) * ATT_LD + row] = qv.w;
    }

    float m_i[8], l_i[8], acc[8][8];
    #pragma unroll
    for (int i = 0; i < 8; i++) {
        m_i[i] = -1e30f; l_i[i] = 0.f;
        #pragma unroll
        for (int j = 0; j < 8; j++) acc[i][j] = 0.f;
    }

    for (int kt = 0; kt <= qi; kt++) {
        const int k0 = kt * 64;
        __syncthreads();   // previous PV reads of Ks/Vs/Ps done
        #pragma unroll
        for (int i = 0; i < 16; i++) {
            const int f = i * 64 + t;
            const int row = f >> 4;
            const int e4 = (f & 15) * 4;
            float4 kv = *(const float4*)&kb[(size_t)(k0 + row) * HD + e4];
            Ks[(e4 + 0) * ATT_LD + row] = kv.x;
            Ks[(e4 + 1) * ATT_LD + row] = kv.y;
            Ks[(e4 + 2) * ATT_LD + row] = kv.z;
            Ks[(e4 + 3) * ATT_LD + row] = kv.w;
            float4 vv = *(const float4*)&vb[(size_t)(k0 + row) * HD + e4];
            *(float4*)&Vs[row * ATT_LD + e4] = vv;
        }
        __syncthreads();

        // Scores: s[r][c] = sum_e Q[r][e] * K[c][e]
        float s[8][8];
        #pragma unroll
        for (int i = 0; i < 8; i++)
            #pragma unroll
            for (int j = 0; j < 8; j++) s[i][j] = 0.f;

        for (int e = 0; e < 64; e++) {
            float qa[8], kf[8];
            *(float4*)&qa[0] = *(const float4*)&Qs[e * ATT_LD + ty * 8];
            *(float4*)&qa[4] = *(const float4*)&Qs[e * ATT_LD + ty * 8 + 4];
            *(float4*)&kf[0] = *(const float4*)&Ks[e * ATT_LD + tx * 8];
            *(float4*)&kf[4] = *(const float4*)&Ks[e * ATT_LD + tx * 8 + 4];
            #pragma unroll
            for (int i = 0; i < 8; i++)
                #pragma unroll
                for (int j = 0; j < 8; j++)
                    s[i][j] = fmaf(qa[i], kf[j], s[i][j]);
        }

        // Scale + causal mask (only the diagonal tile needs masking)
        const bool diag = (kt == qi);
        #pragma unroll
        for (int i = 0; i < 8; i++)
            #pragma unroll
            for (int j = 0; j < 8; j++) {
                float val = s[i][j] * 0.125f;   // 1/sqrt(64)
                if (diag && (k0 + tx * 8 + j) > (q0 + ty * 8 + i)) val = -1e30f;
                s[i][j] = val;
            }

        // Online softmax per row (8 lanes share a row-group via shfl width 8)
        #pragma unroll
        for (int i = 0; i < 8; i++) {
            float tm = s[i][0];
            #pragma unroll
            for (int j = 1; j < 8; j++) tm = fmaxf(tm, s[i][j]);
            tm = fmaxf(tm, __shfl_xor_sync(0xffffffffu, tm, 4, 8));
            tm = fmaxf(tm, __shfl_xor_sync(0xffffffffu, tm, 2, 8));
            tm = fmaxf(tm, __shfl_xor_sync(0xffffffffu, tm, 1, 8));
            const float mn = fmaxf(m_i[i], tm);
            const float alpha = __expf(m_i[i] - mn);
            m_i[i] = mn;
            float rs = 0.f;
            #pragma unroll
            for (int j = 0; j < 8; j++) {
                s[i][j] = __expf(s[i][j] - mn);
                rs += s[i][j];
            }
            rs += __shfl_xor_sync(0xffffffffu, rs, 4, 8);
            rs += __shfl_xor_sync(0xffffffffu, rs, 2, 8);
            rs += __shfl_xor_sync(0xffffffffu, rs, 1, 8);
            l_i[i] = l_i[i] * alpha + rs;
            #pragma unroll
            for (int j = 0; j < 8; j++) acc[i][j] *= alpha;
        }

        // Stage P transposed: Ps[j][r]
        #pragma unroll
        for (int i = 0; i < 8; i++)
            #pragma unroll
            for (int j = 0; j < 8; j++)
                Ps[(tx * 8 + j) * ATT_LD + ty * 8 + i] = s[i][j];
        __syncthreads();

        // O += P @ V
        for (int jj = 0; jj < 64; jj++) {
            float pa[8], vf[8];
            *(float4*)&pa[0] = *(const float4*)&Ps[jj * ATT_LD + ty * 8];
            *(float4*)&pa[4] = *(const float4*)&Ps[jj * ATT_LD + ty * 8 + 4];
            *(float4*)&vf[0] = *(const float4*)&Vs[jj * ATT_LD + tx * 8];
            *(float4*)&vf[4] = *(const float4*)&Vs[jj * ATT_LD + tx * 8 + 4];
            #pragma unroll
            for (int i = 0; i < 8; i++)
                #pragma unroll
                for (int j = 0; j < 8; j++)
                    acc[i][j] = fmaf(pa[i], vf[j], acc[i][j]);
        }
    }

    // Epilogue: normalize and write O in [B,S,D] (heads concatenated)
    const int b = bhid >> 4, h = bhid & 15;
    #pragma unroll
    for (int i = 0; i < 8; i++) {
        const float inv = 1.f / l_i[i];
        const int srow = q0 + ty * 8 + i;
        float4 o0, o1;
        o0.x = acc[i][0] * inv; o0.y = acc[i][1] * inv;
        o0.z = acc[i][2] * inv; o0.w = acc[i][3] * inv;
        o1.x = acc[i][4] * inv; o1.y = acc[i][5] * inv;
        o1.z = acc[i][6] * inv; o1.w = acc[i][7] * inv;
        float* op = &g_o[((size_t)(b * Ss + srow)) * Dd + h * HD + tx * 8];
        *(float4*)&op[0] = o0;
        *(float4*)&op[4] = o1;
    }
}

// ---------------------------------------------------------------------------
// Launch
// ---------------------------------------------------------------------------
extern "C" void kernel_launch(void* const* d_in, const int* in_sizes, int n_in,
                              void* d_out, int out_size)
{
    const float* x  = (const float*)d_in[0];
    const float* Wq = (const float*)d_in[1];
    const float* bq = (const float*)d_in[2];
    const float* Wk = (const float*)d_in[3];
    const float* bk = (const float*)d_in[4];
    const float* Wv = (const float*)d_in[5];
    const float* bv = (const float*)d_in[6];
    const float* Wp = (const float*)d_in[7];
    const float* bp = (const float*)d_in[8];
    float* out = (float*)d_out;

    cudaFuncSetAttribute(attn_kernel,
                         cudaFuncAttributeMaxDynamicSharedMemorySize, ATT_SMEM);

    // 1) QKV projection: grid (N/128=24, M/128=64)
    qkv_gemm<<<dim3(24, 64), 256>>>(x, Wq, Wk, Wv, bq, bk, bv);

    // 2) Attention: grid (32 q-tiles, 64 bh pairs)
    attn_kernel<<<dim3(32, 64), 64, ATT_SMEM>>>();

    // 3) Output projection: grid (N/128=8, M/128=64)
    proj_gemm<<<dim3(8, 64), 256>>>(Wp, bp, out);
}

// round 5
// speedup vs baseline: 1.7431x; 1.7431x over previous
#include <cuda_runtime.h>
#include <cuda_bf16.h>
#include <cstdint>

// ---------------------------------------------------------------------------
// Problem constants
// ---------------------------------------------------------------------------
constexpr int Bc = 4;
constexpr int Ss = 2048;
constexpr int Dd = 1024;
constexpr int Hh = 16;
constexpr int HD = 64;
constexpr int Mtot = Bc * Ss;          // 8192
constexpr int Nqkv = 3 * Dd;           // 3072

// ---------------------------------------------------------------------------
// Scratch (device globals — referenced ONLY from device code)
// ---------------------------------------------------------------------------
__device__ float g_q[(size_t)Bc * Hh * Ss * HD];   // [B,H,S,HD]
__device__ float g_k[(size_t)Bc * Hh * Ss * HD];
__device__ float g_v[(size_t)Bc * Hh * Ss * HD];
__device__ float g_o[(size_t)Mtot * Dd];           // [B,S,D]

__device__ __nv_bfloat16 g_xh[(size_t)Mtot * Dd];
__device__ __nv_bfloat16 g_xl[(size_t)Mtot * Dd];
__device__ __nv_bfloat16 g_oh[(size_t)Mtot * Dd];
__device__ __nv_bfloat16 g_ol[(size_t)Mtot * Dd];
__device__ __nv_bfloat16 g_wth[(size_t)Nqkv * Dd]; // [N=3072][K=1024] (W^T)
__device__ __nv_bfloat16 g_wtl[(size_t)Nqkv * Dd];
__device__ __nv_bfloat16 g_wph[(size_t)Dd * Dd];   // [N=1024][K=1024] (Wp^T)
__device__ __nv_bfloat16 g_wpl[(size_t)Dd * Dd];
__device__ float g_bias[Nqkv];

// ---------------------------------------------------------------------------
// PTX helpers (baseline ISA only — must assemble at .target sm_100)
// ---------------------------------------------------------------------------
__device__ __forceinline__ uint32_t s2u(const void* p) {
    uint32_t a;
    asm("{ .reg .u64 t; cvta.to.shared.u64 t, %1; cvt.u32.u64 %0, t; }"
        : "=r"(a) : "l"(p));
    return a;
}
__device__ __forceinline__ void cpasync16(uint32_t dst, const void* src) {
    asm volatile("cp.async.cg.shared.global [%0], [%1], 16;"
                 :: "r"(dst), "l"(src) : "memory");
}
__device__ __forceinline__ void cpcommit() {
    asm volatile("cp.async.commit_group;" ::: "memory");
}
template<int N> __device__ __forceinline__ void cpwait() {
    asm volatile("cp.async.wait_group %0;" :: "n"(N) : "memory");
}
__device__ __forceinline__ void ldsm4(uint32_t* r, uint32_t addr) {
    asm volatile("ldmatrix.sync.aligned.m8n8.x4.shared.b16 {%0,%1,%2,%3}, [%4];"
                 : "=r"(r[0]), "=r"(r[1]), "=r"(r[2]), "=r"(r[3]) : "r"(addr));
}
__device__ __forceinline__ void mma16816(float* c, const uint32_t* a, const uint32_t* b) {
    asm volatile("mma.sync.aligned.m16n8k16.row.col.f32.bf16.bf16.f32 "
                 "{%0,%1,%2,%3}, {%4,%5,%6,%7}, {%8,%9}, {%0,%1,%2,%3};"
                 : "+f"(c[0]), "+f"(c[1]), "+f"(c[2]), "+f"(c[3])
                 : "r"(a[0]), "r"(a[1]), "r"(a[2]), "r"(a[3]),
                   "r"(b[0]), "r"(b[1]));
}

// ---------------------------------------------------------------------------
// Conversion kernels (scratch selected in DEVICE code via template)
// ---------------------------------------------------------------------------
// SRC 0: src = x (param)  -> g_xh/g_xl
// SRC 1: src = g_o        -> g_oh/g_ol
template<int SRC>
__global__ void k_f32_to_bf16x2(const float* __restrict__ xsrc, int n4)
{
    const float* src = (SRC == 0) ? xsrc : g_o;
    __nv_bfloat16* hi = (SRC == 0) ? g_xh : g_oh;
    __nv_bfloat16* lo = (SRC == 0) ? g_xl : g_ol;
    int i = blockIdx.x * blockDim.x + threadIdx.x;
    if (i >= n4) return;
    float4 v = ((const float4*)src)[i];
    __nv_bfloat16 h0 = __float2bfloat16(v.x), h1 = __float2bfloat16(v.y);
    __nv_bfloat16 h2 = __float2bfloat16(v.z), h3 = __float2bfloat16(v.w);
    __nv_bfloat16 l0 = __float2bfloat16(v.x - __bfloat162float(h0));
    __nv_bfloat16 l1 = __float2bfloat16(v.y - __bfloat162float(h1));
    __nv_bfloat16 l2 = __float2bfloat16(v.z - __bfloat162float(h2));
    __nv_bfloat16 l3 = __float2bfloat16(v.w - __bfloat162float(h3));
    ((__nv_bfloat162*)hi)[2 * i]     = __halves2bfloat162(h0, h1);
    ((__nv_bfloat162*)hi)[2 * i + 1] = __halves2bfloat162(h2, h3);
    ((__nv_bfloat162*)lo)[2 * i]     = __halves2bfloat162(l0, l1);
    ((__nv_bfloat162*)lo)[2 * i + 1] = __halves2bfloat162(l2, l3);
}

// W[h][d][e] (per part) -> g_wth/g_wtl[(p,h,e)][d]  (transpose into K-major)
__global__ void k_conv_wqkv(const float* __restrict__ Wq,
                            const float* __restrict__ Wk,
                            const float* __restrict__ Wv)
{
    __shared__ float sm[64 * 65];
    const int d0 = blockIdx.x * 64, h = blockIdx.y, p = blockIdx.z;
    const float* W = (p == 0) ? Wq : (p == 1) ? Wk : Wv;
    const int tid = threadIdx.x;
    #pragma unroll
    for (int t = 0; t < 16; t++) {
        int idx = tid + t * 256;   // 0..4095
        int r = idx >> 6, e = idx & 63;
        sm[r * 65 + e] = W[((size_t)h * Dd + d0 + r) * HD + e];
    }
    __syncthreads();
    #pragma unroll
    for (int t = 0; t < 16; t++) {
        int idx = tid + t * 256;
        int e = idx >> 6, r = idx & 63;
        float v = sm[r * 65 + e];
        __nv_bfloat16 hi = __float2bfloat16(v);
        __nv_bfloat16 lo = __float2bfloat16(v - __bfloat162float(hi));
        size_t n = (size_t)p * 1024 + h * 64 + e;
        g_wth[n * Dd + d0 + r] = hi;
        g_wtl[n * Dd + d0 + r] = lo;
    }
}

// Wp[k][n] -> g_wph/g_wpl[n][k]
__global__ void k_conv_wp(const float* __restrict__ Wp)
{
    __shared__ float sm[64 * 65];
    const int n0 = blockIdx.x * 64, k0 = blockIdx.y * 64;
    const int tid = threadIdx.x;
    #pragma unroll
    for (int t = 0; t < 16; t++) {
        int idx = tid + t * 256;
        int r = idx >> 6, e = idx & 63;        // r: k, e: n
        sm[r * 65 + e] = Wp[(size_t)(k0 + r) * Dd + n0 + e];
    }
    __syncthreads();
    #pragma unroll
    for (int t = 0; t < 16; t++) {
        int idx = tid + t * 256;
        int e = idx >> 6, r = idx & 63;
        float v = sm[r * 65 + e];
        __nv_bfloat16 hi = __float2bfloat16(v);
        __nv_bfloat16 lo = __float2bfloat16(v - __bfloat162float(hi));
        size_t n = (size_t)(n0 + e);
        g_wph[n * Dd + k0 + r] = hi;
        g_wpl[n * Dd + k0 + r] = lo;
    }
}

__global__ void k_bias(const float* __restrict__ bq, const float* __restrict__ bk,
                       const float* __restrict__ bv)
{
    int i = blockIdx.x * 256 + threadIdx.x;
    if (i < Nqkv)
        g_bias[i] = (i < 1024) ? bq[i] : (i < 2048) ? bk[i - 1024] : bv[i - 2048];
}

// ---------------------------------------------------------------------------
// mma.sync bf16 split-precision GEMM: D fp32 += aH*bH + aH*bL + aL*bH
// A: [M][K] row-major bf16 hi/lo, B: [N][K] row-major bf16 hi/lo (K-major).
// CTA tile 128x128, BK=32, 256 threads = 8 warps (4m x 2n), warp tile 32x64.
// cp.async double-buffered; ldmatrix with 16B XOR swizzle.
// All scratch operands selected in DEVICE code:
//   MODE 0 (proj): A=g_oh/g_ol, B=g_wph/g_wpl, bias=param, out=param
//   MODE 1 (qkv):  A=g_xh/g_xl, B=g_wth/g_wtl, bias=g_bias, out=g_q/g_k/g_v
// ---------------------------------------------------------------------------
constexpr int GK = 1024;
constexpr int BK = 32;
constexpr int NCHUNK = GK / BK;                 // 32
constexpr int TILE_B = 128 * BK * 2;            // 8192 bytes per (tensor, prec) tile
constexpr int STAGE_B = 4 * TILE_B;             // 32768 (Ah, Al, Bh, Bl)
constexpr int GEMM_SMEM = 2 * STAGE_B;          // 65536

// swizzled byte offset within a tile for (row, 16B-chunk c in 0..3)
__device__ __forceinline__ uint32_t tswz(int row, int c) {
    return (uint32_t)(row * 64 + ((c ^ (row & 3)) << 4));
}

template<int MODE>
__global__ __launch_bounds__(256)
void gemm_bf16x3(const float* __restrict__ bias_p, float* __restrict__ out)
{
    const __nv_bfloat16* Ah = (MODE == 0) ? g_oh : g_xh;
    const __nv_bfloat16* Al = (MODE == 0) ? g_ol : g_xl;
    const __nv_bfloat16* Bh = (MODE == 0) ? g_wph : g_wth;
    const __nv_bfloat16* Bl = (MODE == 0) ? g_wpl : g_wtl;
    const float* bias = (MODE == 0) ? bias_p : g_bias;

    extern __shared__ __align__(128) char smem[];
    const uint32_t sb = s2u(smem);
    const int tid = threadIdx.x;
    const int wid = tid >> 5, lane = tid & 31;
    const int warp_m = wid & 3;                 // 0..3 -> m offset 32*warp_m
    const int warp_n = wid >> 2;                // 0..1 -> n offset 64*warp_n
    const int m0 = blockIdx.y * 128, n0 = blockIdx.x * 128;

    float acc[2][8][4];
    #pragma unroll
    for (int i = 0; i < 2; i++)
        #pragma unroll
        for (int j = 0; j < 8; j++)
            #pragma unroll
            for (int r = 0; r < 4; r++) acc[i][j][r] = 0.f;

    auto load_chunk = [&](int stage, int kc) {
        uint32_t sbase = sb + stage * STAGE_B;
        #pragma unroll
        for (int t4 = 0; t4 < 4; t4++) {
            const __nv_bfloat16* base =
                (t4 == 0) ? Ah : (t4 == 1) ? Al : (t4 == 2) ? Bh : Bl;
            const int r0 = (t4 < 2) ? m0 : n0;
            const uint32_t tbase = sbase + t4 * TILE_B;
            #pragma unroll
            for (int v = 0; v < 2; v++) {
                int id = tid + v * 256;          // 0..511
                int row = id >> 2, c = id & 3;   // 128 rows x 4 x 16B
                const void* src = base + (size_t)(r0 + row) * GK + kc * BK + c * 8;
                cpasync16(tbase + tswz(row, c), src);
            }
        }
        cpcommit();
    };

    // ldmatrix lane-address components (constant across chunks)
    const int a_row = warp_m * 32 + (lane & 15);       // + mt*16
    const int a_cb  = lane >> 4;                       // + ks*2
    const int b_j   = lane >> 3;
    const int b_row = warp_n * 64 + ((b_j >> 1) << 3) + (lane & 7);  // + np*16
    const int b_cb  = b_j & 1;                         // + ks*2

    load_chunk(0, 0);

    for (int i = 0; i < NCHUNK; i++) {
        const int s = i & 1;
        if (i + 1 < NCHUNK) {
            load_chunk(1 - s, i + 1);
            cpwait<1>();               // chunk i resident
        } else {
            cpwait<0>();
        }
        __syncthreads();               // chunk i visible to all warps

        const uint32_t tAh = sb + s * STAGE_B;
        const uint32_t tAl = tAh + TILE_B;
        const uint32_t tBh = tAh + 2 * TILE_B;
        const uint32_t tBl = tAh + 3 * TILE_B;

        #pragma unroll
        for (int ks = 0; ks < 2; ks++) {
            uint32_t ah[2][4], al[2][4];
            #pragma unroll
            for (int mt = 0; mt < 2; mt++) {
                const uint32_t off = tswz(a_row + mt * 16, ks * 2 + a_cb);
                ldsm4(ah[mt], tAh + off);
                ldsm4(al[mt], tAl + off);
            }
            #pragma unroll
            for (int np = 0; np < 4; np++) {
                const uint32_t off = tswz(b_row + np * 16, ks * 2 + b_cb);
                uint32_t bh[4], bl[4];
                ldsm4(bh, tBh + off);
                ldsm4(bl, tBl + off);
                #pragma unroll
                for (int mt = 0; mt < 2; mt++) {
                    #pragma unroll
                    for (int nt = 0; nt < 2; nt++) {
                        float* c = acc[mt][np * 2 + nt];
                        mma16816(c, ah[mt], &bh[nt * 2]);
                        mma16816(c, ah[mt], &bl[nt * 2]);
                        mma16816(c, al[mt], &bh[nt * 2]);
                    }
                }
            }
        }
        __syncthreads();               // all reads of stage s done before reuse
    }

    // Epilogue from C fragments: lane holds rows {g, g+8}, cols {2t, 2t+1}
    const int g = lane >> 2, t2 = (lane & 3) * 2;
    #pragma unroll
    for (int mt = 0; mt < 2; mt++) {
        #pragma unroll
        for (int nt = 0; nt < 8; nt++) {
            const int ncol = n0 + warp_n * 64 + nt * 8 + t2;   // global col (pair)
            #pragma unroll
            for (int rh = 0; rh < 2; rh++) {
                const int m = m0 + warp_m * 32 + mt * 16 + g + rh * 8;
                float2 v;
                v.x = acc[mt][nt][rh * 2 + 0] + bias[ncol];
                v.y = acc[mt][nt][rh * 2 + 1] + bias[ncol + 1];
                if (MODE == 0) {
                    *(float2*)&out[(size_t)m * Dd + ncol] = v;
                } else {
                    const int part = ncol >> 10;
                    const int nn = ncol & 1023;
                    const int h = nn >> 6, e = nn & 63;
                    float* dstp = (part == 0) ? g_q : (part == 1) ? g_k : g_v;
                    const int b = m >> 11, s_ = m & 2047;
                    *(float2*)&dstp[(((size_t)(b * Hh + h) * Ss + s_) * HD + e)] = v;
                }
            }
        }
    }
}

// ---------------------------------------------------------------------------
// Causal flash attention (fp32, validated round 1)
// ---------------------------------------------------------------------------
constexpr int ATT_LD = 68;
constexpr int ATT_SMEM = 4 * 64 * ATT_LD * 4;

__global__ __launch_bounds__(64) void attn_kernel()
{
    extern __shared__ float sm[];
    float* Qs = sm;
    float* Ks = sm + 64 * ATT_LD;
    float* Vs = sm + 2 * 64 * ATT_LD;
    float* Ps = sm + 3 * 64 * ATT_LD;

    const int bhid = blockIdx.y;
    const int qi = (int)gridDim.x - 1 - (int)blockIdx.x;
    const int q0 = qi * 64;

    const float* qb = g_q + (size_t)bhid * Ss * HD;
    const float* kb = g_k + (size_t)bhid * Ss * HD;
    const float* vb = g_v + (size_t)bhid * Ss * HD;

    const int t = threadIdx.x;
    const int ty = t >> 3, tx = t & 7;

    #pragma unroll
    for (int i = 0; i < 16; i++) {
        const int f = i * 64 + t;
        const int row = f >> 4;
        const int e4 = (f & 15) * 4;
        float4 qv = *(const float4*)&qb[(size_t)(q0 + row) * HD + e4];
        Qs[(e4 + 0) * ATT_LD + row] = qv.x;
        Qs[(e4 + 1) * ATT_LD + row] = qv.y;
        Qs[(e4 + 2) * ATT_LD + row] = qv.z;
        Qs[(e4 + 3) * ATT_LD + row] = qv.w;
    }

    float m_i[8], l_i[8], acc[8][8];
    #pragma unroll
    for (int i = 0; i < 8; i++) {
        m_i[i] = -1e30f; l_i[i] = 0.f;
        #pragma unroll
        for (int j = 0; j < 8; j++) acc[i][j] = 0.f;
    }

    for (int kt = 0; kt <= qi; kt++) {
        const int k0 = kt * 64;
        __syncthreads();
        #pragma unroll
        for (int i = 0; i < 16; i++) {
            const int f = i * 64 + t;
            const int row = f >> 4;
            const int e4 = (f & 15) * 4;
            float4 kv = *(const float4*)&kb[(size_t)(k0 + row) * HD + e4];
            Ks[(e4 + 0) * ATT_LD + row] = kv.x;
            Ks[(e4 + 1) * ATT_LD + row] = kv.y;
            Ks[(e4 + 2) * ATT_LD + row] = kv.z;
            Ks[(e4 + 3) * ATT_LD + row] = kv.w;
            float4 vv = *(const float4*)&vb[(size_t)(k0 + row) * HD + e4];
            *(float4*)&Vs[row * ATT_LD + e4] = vv;
        }
        __syncthreads();

        float s[8][8];
        #pragma unroll
        for (int i = 0; i < 8; i++)
            #pragma unroll
            for (int j = 0; j < 8; j++) s[i][j] = 0.f;

        for (int e = 0; e < 64; e++) {
            float qa[8], kf[8];
            *(float4*)&qa[0] = *(const float4*)&Qs[e * ATT_LD + ty * 8];
            *(float4*)&qa[4] = *(const float4*)&Qs[e * ATT_LD + ty * 8 + 4];
            *(float4*)&kf[0] = *(const float4*)&Ks[e * ATT_LD + tx * 8];
            *(float4*)&kf[4] = *(const float4*)&Ks[e * ATT_LD + tx * 8 + 4];
            #pragma unroll
            for (int i = 0; i < 8; i++)
                #pragma unroll
                for (int j = 0; j < 8; j++)
                    s[i][j] = fmaf(qa[i], kf[j], s[i][j]);
        }

        const bool diag = (kt == qi);
        #pragma unroll
        for (int i = 0; i < 8; i++)
            #pragma unroll
            for (int j = 0; j < 8; j++) {
                float val = s[i][j] * 0.125f;
                if (diag && (k0 + tx * 8 + j) > (q0 + ty * 8 + i)) val = -1e30f;
                s[i][j] = val;
            }

        #pragma unroll
        for (int i = 0; i < 8; i++) {
            float tm = s[i][0];
            #pragma unroll
            for (int j = 1; j < 8; j++) tm = fmaxf(tm, s[i][j]);
            tm = fmaxf(tm, __shfl_xor_sync(0xffffffffu, tm, 4, 8));
            tm = fmaxf(tm, __shfl_xor_sync(0xffffffffu, tm, 2, 8));
            tm = fmaxf(tm, __shfl_xor_sync(0xffffffffu, tm, 1, 8));
            const float mn = fmaxf(m_i[i], tm);
            const float alpha = __expf(m_i[i] - mn);
            m_i[i] = mn;
            float rs = 0.f;
            #pragma unroll
            for (int j = 0; j < 8; j++) {
                s[i][j] = __expf(s[i][j] - mn);
                rs += s[i][j];
            }
            rs += __shfl_xor_sync(0xffffffffu, rs, 4, 8);
            rs += __shfl_xor_sync(0xffffffffu, rs, 2, 8);
            rs += __shfl_xor_sync(0xffffffffu, rs, 1, 8);
            l_i[i] = l_i[i] * alpha + rs;
            #pragma unroll
            for (int j = 0; j < 8; j++) acc[i][j] *= alpha;
        }

        #pragma unroll
        for (int i = 0; i < 8; i++)
            #pragma unroll
            for (int j = 0; j < 8; j++)
                Ps[(tx * 8 + j) * ATT_LD + ty * 8 + i] = s[i][j];
        __syncthreads();

        for (int jj = 0; jj < 64; jj++) {
            float pa[8], vf[8];
            *(float4*)&pa[0] = *(const float4*)&Ps[jj * ATT_LD + ty * 8];
            *(float4*)&pa[4] = *(const float4*)&Ps[jj * ATT_LD + ty * 8 + 4];
            *(float4*)&vf[0] = *(const float4*)&Vs[jj * ATT_LD + tx * 8];
            *(float4*)&vf[4] = *(const float4*)&Vs[jj * ATT_LD + tx * 8 + 4];
            #pragma unroll
            for (int i = 0; i < 8; i++)
                #pragma unroll
                for (int j = 0; j < 8; j++)
                    acc[i][j] = fmaf(pa[i], vf[j], acc[i][j]);
        }
    }

    const int b = bhid >> 4, h = bhid & 15;
    #pragma unroll
    for (int i = 0; i < 8; i++) {
        const float inv = 1.f / l_i[i];
        const int srow = q0 + ty * 8 + i;
        float4 o0, o1;
        o0.x = acc[i][0] * inv; o0.y = acc[i][1] * inv;
        o0.z = acc[i][2] * inv; o0.w = acc[i][3] * inv;
        o1.x = acc[i][4] * inv; o1.y = acc[i][5] * inv;
        o1.z = acc[i][6] * inv; o1.w = acc[i][7] * inv;
        float* op = &g_o[((size_t)(b * Ss + srow)) * Dd + h * HD + tx * 8];
        *(float4*)&op[0] = o0;
        *(float4*)&op[4] = o1;
    }
}

// ---------------------------------------------------------------------------
// Launch — only harness pointers cross the host/device boundary
// ---------------------------------------------------------------------------
extern "C" void kernel_launch(void* const* d_in, const int* in_sizes, int n_in,
                              void* d_out, int out_size)
{
    const float* x  = (const float*)d_in[0];
    const float* Wq = (const float*)d_in[1];
    const float* bq = (const float*)d_in[2];
    const float* Wk = (const float*)d_in[3];
    const float* bk = (const float*)d_in[4];
    const float* Wv = (const float*)d_in[5];
    const float* bv = (const float*)d_in[6];
    const float* Wp = (const float*)d_in[7];
    const float* bp = (const float*)d_in[8];
    float* out = (float*)d_out;

    cudaFuncSetAttribute(gemm_bf16x3<0>,
                         cudaFuncAttributeMaxDynamicSharedMemorySize, GEMM_SMEM);
    cudaFuncSetAttribute(gemm_bf16x3<1>,
                         cudaFuncAttributeMaxDynamicSharedMemorySize, GEMM_SMEM);
    cudaFuncSetAttribute(attn_kernel,
                         cudaFuncAttributeMaxDynamicSharedMemorySize, ATT_SMEM);

    // Conversions
    const int n4 = Mtot * Dd / 4;
    k_f32_to_bf16x2<0><<<(n4 + 255) / 256, 256>>>(x, n4);   // x -> g_xh/g_xl
    k_conv_wqkv<<<dim3(16, 16, 3), 256>>>(Wq, Wk, Wv);
    k_conv_wp<<<dim3(16, 16), 256>>>(Wp);
    k_bias<<<12, 256>>>(bq, bk, bv);

    // QKV projection (mma.sync): grid (3072/128=24, 8192/128=64)
    gemm_bf16x3<1><<<dim3(24, 64), 256, GEMM_SMEM>>>(nullptr, nullptr);

    // Attention
    attn_kernel<<<dim3(32, 64), 64, ATT_SMEM>>>();

    // g_o -> g_oh/g_ol, then output projection (mma.sync)
    k_f32_to_bf16x2<1><<<(n4 + 255) / 256, 256>>>(nullptr, n4);
    gemm_bf16x3<0><<<dim3(8, 64), 256, GEMM_SMEM>>>(bp, out);
}

// round 7
// speedup vs baseline: 3.3259x; 1.9081x over previous
#include <cuda_runtime.h>
#include <cuda_bf16.h>
#include <cstdint>

// ---------------------------------------------------------------------------
// Problem constants
// ---------------------------------------------------------------------------
constexpr int Bc = 4;
constexpr int Ss = 2048;
constexpr int Dd = 1024;
constexpr int Hh = 16;
constexpr int HD = 64;
constexpr int Mtot = Bc * Ss;          // 8192
constexpr int Nqkv = 3 * Dd;           // 3072

// ---------------------------------------------------------------------------
// Scratch (device globals — referenced ONLY from device code)
// ---------------------------------------------------------------------------
__device__ __nv_bfloat16 g_qh[(size_t)Bc * Hh * Ss * HD];  // [B,H,S,HD]
__device__ __nv_bfloat16 g_ql[(size_t)Bc * Hh * Ss * HD];
__device__ __nv_bfloat16 g_kh[(size_t)Bc * Hh * Ss * HD];
__device__ __nv_bfloat16 g_kl[(size_t)Bc * Hh * Ss * HD];
__device__ __nv_bfloat16 g_vh[(size_t)Bc * Hh * Ss * HD];  // [B,H,S,HD] (same as K)
__device__ __nv_bfloat16 g_vl[(size_t)Bc * Hh * Ss * HD];

__device__ __nv_bfloat16 g_xh[(size_t)Mtot * Dd];
__device__ __nv_bfloat16 g_xl[(size_t)Mtot * Dd];
__device__ __nv_bfloat16 g_oh[(size_t)Mtot * Dd];          // attention out hi/lo
__device__ __nv_bfloat16 g_ol[(size_t)Mtot * Dd];
__device__ __nv_bfloat16 g_wth[(size_t)Nqkv * Dd];         // [N=3072][K=1024] (W^T)
__device__ __nv_bfloat16 g_wtl[(size_t)Nqkv * Dd];
__device__ __nv_bfloat16 g_wph[(size_t)Dd * Dd];           // [N=1024][K=1024] (Wp^T)
__device__ __nv_bfloat16 g_wpl[(size_t)Dd * Dd];
__device__ float g_bias[Nqkv];

// ---------------------------------------------------------------------------
// PTX helpers (baseline ISA only — assembles at .target sm_100)
// ---------------------------------------------------------------------------
__device__ __forceinline__ uint32_t s2u(const void* p) {
    uint32_t a;
    asm("{ .reg .u64 t; cvta.to.shared.u64 t, %1; cvt.u32.u64 %0, t; }"
        : "=r"(a) : "l"(p));
    return a;
}
__device__ __forceinline__ void cpasync16(uint32_t dst, const void* src) {
    asm volatile("cp.async.cg.shared.global [%0], [%1], 16;"
                 :: "r"(dst), "l"(src) : "memory");
}
__device__ __forceinline__ void cpcommit() {
    asm volatile("cp.async.commit_group;" ::: "memory");
}
template<int N> __device__ __forceinline__ void cpwait() {
    asm volatile("cp.async.wait_group %0;" :: "n"(N) : "memory");
}
__device__ __forceinline__ void ldsm4(uint32_t* r, uint32_t addr) {
    asm volatile("ldmatrix.sync.aligned.m8n8.x4.shared.b16 {%0,%1,%2,%3}, [%4];"
                 : "=r"(r[0]), "=r"(r[1]), "=r"(r[2]), "=r"(r[3]) : "r"(addr));
}
__device__ __forceinline__ void ldsm4t(uint32_t* r, uint32_t addr) {
    asm volatile("ldmatrix.sync.aligned.m8n8.x4.trans.shared.b16 {%0,%1,%2,%3}, [%4];"
                 : "=r"(r[0]), "=r"(r[1]), "=r"(r[2]), "=r"(r[3]) : "r"(addr));
}
__device__ __forceinline__ void mma16816(float* c, const uint32_t* a, const uint32_t* b) {
    asm volatile("mma.sync.aligned.m16n8k16.row.col.f32.bf16.bf16.f32 "
                 "{%0,%1,%2,%3}, {%4,%5,%6,%7}, {%8,%9}, {%0,%1,%2,%3};"
                 : "+f"(c[0]), "+f"(c[1]), "+f"(c[2]), "+f"(c[3])
                 : "r"(a[0]), "r"(a[1]), "r"(a[2]), "r"(a[3]),
                   "r"(b[0]), "r"(b[1]));
}
__device__ __forceinline__ uint32_t packbf(__nv_bfloat16 x, __nv_bfloat16 y) {
    __nv_bfloat162 t = __halves2bfloat162(x, y);
    return *(uint32_t*)&t;
}

// ---------------------------------------------------------------------------
// Conversion kernels
// ---------------------------------------------------------------------------
__global__ void k_conv_x(const float* __restrict__ src, int n4)
{
    int i = blockIdx.x * blockDim.x + threadIdx.x;
    if (i >= n4) return;
    float4 v = ((const float4*)src)[i];
    __nv_bfloat16 h0 = __float2bfloat16(v.x), h1 = __float2bfloat16(v.y);
    __nv_bfloat16 h2 = __float2bfloat16(v.z), h3 = __float2bfloat16(v.w);
    __nv_bfloat16 l0 = __float2bfloat16(v.x - __bfloat162float(h0));
    __nv_bfloat16 l1 = __float2bfloat16(v.y - __bfloat162float(h1));
    __nv_bfloat16 l2 = __float2bfloat16(v.z - __bfloat162float(h2));
    __nv_bfloat16 l3 = __float2bfloat16(v.w - __bfloat162float(h3));
    ((__nv_bfloat162*)g_xh)[2 * i]     = __halves2bfloat162(h0, h1);
    ((__nv_bfloat162*)g_xh)[2 * i + 1] = __halves2bfloat162(h2, h3);
    ((__nv_bfloat162*)g_xl)[2 * i]     = __halves2bfloat162(l0, l1);
    ((__nv_bfloat162*)g_xl)[2 * i + 1] = __halves2bfloat162(l2, l3);
}

// W[h][d][e] (per part) -> g_wth/g_wtl[(p,h,e)][d]  (transpose into K-major)
__global__ void k_conv_wqkv(const float* __restrict__ Wq,
                            const float* __restrict__ Wk,
                            const float* __restrict__ Wv)
{
    __shared__ float sm[64 * 65];
    const int d0 = blockIdx.x * 64, h = blockIdx.y, p = blockIdx.z;
    const float* W = (p == 0) ? Wq : (p == 1) ? Wk : Wv;
    const int tid = threadIdx.x;
    #pragma unroll
    for (int t = 0; t < 16; t++) {
        int idx = tid + t * 256;
        int r = idx >> 6, e = idx & 63;
        sm[r * 65 + e] = W[((size_t)h * Dd + d0 + r) * HD + e];
    }
    __syncthreads();
    #pragma unroll
    for (int t = 0; t < 16; t++) {
        int idx = tid + t * 256;
        int e = idx >> 6, r = idx & 63;
        float v = sm[r * 65 + e];
        __nv_bfloat16 hi = __float2bfloat16(v);
        __nv_bfloat16 lo = __float2bfloat16(v - __bfloat162float(hi));
        size_t n = (size_t)p * 1024 + h * 64 + e;
        g_wth[n * Dd + d0 + r] = hi;
        g_wtl[n * Dd + d0 + r] = lo;
    }
}

// Wp[k][n] -> g_wph/g_wpl[n][k]
__global__ void k_conv_wp(const float* __restrict__ Wp)
{
    __shared__ float sm[64 * 65];
    const int n0 = blockIdx.x * 64, k0 = blockIdx.y * 64;
    const int tid = threadIdx.x;
    #pragma unroll
    for (int t = 0; t < 16; t++) {
        int idx = tid + t * 256;
        int r = idx >> 6, e = idx & 63;
        sm[r * 65 + e] = Wp[(size_t)(k0 + r) * Dd + n0 + e];
    }
    __syncthreads();
    #pragma unroll
    for (int t = 0; t < 16; t++) {
        int idx = tid + t * 256;
        int e = idx >> 6, r = idx & 63;
        float v = sm[r * 65 + e];
        __nv_bfloat16 hi = __float2bfloat16(v);
        __nv_bfloat16 lo = __float2bfloat16(v - __bfloat162float(hi));
        size_t n = (size_t)(n0 + e);
        g_wph[n * Dd + k0 + r] = hi;
        g_wpl[n * Dd + k0 + r] = lo;
    }
}

__global__ void k_bias(const float* __restrict__ bq, const float* __restrict__ bk,
                       const float* __restrict__ bv)
{
    int i = blockIdx.x * 256 + threadIdx.x;
    if (i < Nqkv)
        g_bias[i] = (i < 1024) ? bq[i] : (i < 2048) ? bk[i - 1024] : bv[i - 2048];
}

// ---------------------------------------------------------------------------
// mma.sync bf16 split-precision GEMM (validated R5): D fp32 += aH*bH+aH*bL+aL*bH
//   MODE 0 (proj): A=g_oh/g_ol, B=g_wph/g_wpl, bias=param, out=param (fp32)
//   MODE 1 (qkv):  A=g_xh/g_xl, B=g_wth/g_wtl, bias=g_bias,
//                  out = bf16 hi/lo into g_{q,k,v}{h,l} [B,H,S,HD] (uniform path)
// ---------------------------------------------------------------------------
constexpr int GK = 1024;
constexpr int BK = 32;
constexpr int NCHUNK = GK / BK;                 // 32
constexpr int TILE_B = 128 * BK * 2;            // 8192
constexpr int STAGE_B = 4 * TILE_B;             // 32768
constexpr int GEMM_SMEM = 2 * STAGE_B;          // 65536

__device__ __forceinline__ uint32_t tswz(int row, int c) {
    return (uint32_t)(row * 64 + ((c ^ (row & 3)) << 4));
}

template<int MODE>
__global__ __launch_bounds__(256)
void gemm_bf16x3(const float* __restrict__ bias_p, float* __restrict__ out)
{
    const __nv_bfloat16* Ah = (MODE == 0) ? g_oh : g_xh;
    const __nv_bfloat16* Al = (MODE == 0) ? g_ol : g_xl;
    const __nv_bfloat16* Bh = (MODE == 0) ? g_wph : g_wth;
    const __nv_bfloat16* Bl = (MODE == 0) ? g_wpl : g_wtl;
    const float* bias = (MODE == 0) ? bias_p : g_bias;

    extern __shared__ __align__(128) char smem[];
    const uint32_t sb = s2u(smem);
    const int tid = threadIdx.x;
    const int wid = tid >> 5, lane = tid & 31;
    const int warp_m = wid & 3;
    const int warp_n = wid >> 2;
    const int m0 = blockIdx.y * 128, n0 = blockIdx.x * 128;

    float acc[2][8][4];
    #pragma unroll
    for (int i = 0; i < 2; i++)
        #pragma unroll
        for (int j = 0; j < 8; j++)
            #pragma unroll
            for (int r = 0; r < 4; r++) acc[i][j][r] = 0.f;

    auto load_chunk = [&](int stage, int kc) {
        uint32_t sbase = sb + stage * STAGE_B;
        #pragma unroll
        for (int t4 = 0; t4 < 4; t4++) {
            const __nv_bfloat16* base =
                (t4 == 0) ? Ah : (t4 == 1) ? Al : (t4 == 2) ? Bh : Bl;
            const int r0 = (t4 < 2) ? m0 : n0;
            const uint32_t tbase = sbase + t4 * TILE_B;
            #pragma unroll
            for (int v = 0; v < 2; v++) {
                int id = tid + v * 256;
                int row = id >> 2, c = id & 3;
                const void* src = base + (size_t)(r0 + row) * GK + kc * BK + c * 8;
                cpasync16(tbase + tswz(row, c), src);
            }
        }
        cpcommit();
    };

    const int a_row = warp_m * 32 + (lane & 15);
    const int a_cb  = lane >> 4;
    const int b_j   = lane >> 3;
    const int b_row = warp_n * 64 + ((b_j >> 1) << 3) + (lane & 7);
    const int b_cb  = b_j & 1;

    load_chunk(0, 0);

    for (int i = 0; i < NCHUNK; i++) {
        const int s = i & 1;
        if (i + 1 < NCHUNK) {
            load_chunk(1 - s, i + 1);
            cpwait<1>();
        } else {
            cpwait<0>();
        }
        __syncthreads();

        const uint32_t tAh = sb + s * STAGE_B;
        const uint32_t tAl = tAh + TILE_B;
        const uint32_t tBh = tAh + 2 * TILE_B;
        const uint32_t tBl = tAh + 3 * TILE_B;

        #pragma unroll
        for (int ks = 0; ks < 2; ks++) {
            uint32_t ah[2][4], al[2][4];
            #pragma unroll
            for (int mt = 0; mt < 2; mt++) {
                const uint32_t off = tswz(a_row + mt * 16, ks * 2 + a_cb);
                ldsm4(ah[mt], tAh + off);
                ldsm4(al[mt], tAl + off);
            }
            #pragma unroll
            for (int np = 0; np < 4; np++) {
                const uint32_t off = tswz(b_row + np * 16, ks * 2 + b_cb);
                uint32_t bh[4], bl[4];
                ldsm4(bh, tBh + off);
                ldsm4(bl, tBl + off);
                #pragma unroll
                for (int mt = 0; mt < 2; mt++) {
                    #pragma unroll
                    for (int nt = 0; nt < 2; nt++) {
                        float* c = acc[mt][np * 2 + nt];
                        mma16816(c, ah[mt], &bh[nt * 2]);
                        mma16816(c, ah[mt], &bl[nt * 2]);
                        mma16816(c, al[mt], &bh[nt * 2]);
                    }
                }
            }
        }
        __syncthreads();
    }

    const int g = lane >> 2, t2 = (lane & 3) * 2;
    #pragma unroll
    for (int mt = 0; mt < 2; mt++) {
        #pragma unroll
        for (int nt = 0; nt < 8; nt++) {
            const int ncol = n0 + warp_n * 64 + nt * 8 + t2;
            #pragma unroll
            for (int rh = 0; rh < 2; rh++) {
                const int m = m0 + warp_m * 32 + mt * 16 + g + rh * 8;
                float vx = acc[mt][nt][rh * 2 + 0] + bias[ncol];
                float vy = acc[mt][nt][rh * 2 + 1] + bias[ncol + 1];
                if (MODE == 0) {
                    float2 v; v.x = vx; v.y = vy;
                    *(float2*)&out[(size_t)m * Dd + ncol] = v;
                } else {
                    const int part = ncol >> 10;
                    const int nn = ncol & 1023;
                    const int h = nn >> 6, e = nn & 63;
                    const int b = m >> 11, s_ = m & 2047;
                    __nv_bfloat16 hx = __float2bfloat16(vx);
                    __nv_bfloat16 hy = __float2bfloat16(vy);
                    __nv_bfloat16 lx = __float2bfloat16(vx - __bfloat162float(hx));
                    __nv_bfloat16 ly = __float2bfloat16(vy - __bfloat162float(hy));
                    __nv_bfloat16* dh = (part == 0) ? g_qh : (part == 1) ? g_kh : g_vh;
                    __nv_bfloat16* dl = (part == 0) ? g_ql : (part == 1) ? g_kl : g_vl;
                    size_t idx = ((size_t)(b * Hh + h) * Ss + s_) * HD + e;
                    *(__nv_bfloat162*)&dh[idx] = __halves2bfloat162(hx, hy);
                    *(__nv_bfloat162*)&dl[idx] = __halves2bfloat162(lx, ly);
                }
            }
        }
    }
}

// ---------------------------------------------------------------------------
// Flash attention on mma.sync, split-precision (3-term) QK^T and PV.
// CTA: one (b,h), 128 q rows. 8 warps x 16 q rows. K-tiles of 64 keys.
// K and V both in [B,H,S,HD]; PV B-operand loaded via ldmatrix.trans.
// Output written as bf16 hi/lo to g_oh/g_ol [B,S,D].
// ---------------------------------------------------------------------------
constexpr int AQT = 128, AKT = 64;
constexpr int AQ_B = 128 * 128;        // Q tile bytes (128 rows x 128B)
constexpr int AT_B = 64 * 128;         // K/V tile bytes
constexpr int ASTAGE_B = 4 * AT_B;     // Kh,Kl,Vh,Vl
constexpr int ATT_SMEM = 2 * AQ_B + 2 * ASTAGE_B;   // 98304

__device__ __forceinline__ uint32_t swz128(int row, int c) {
    return (uint32_t)(row * 128 + ((c ^ (row & 7)) << 4));
}

__global__ __launch_bounds__(256) void attn_mma()
{
    extern __shared__ __align__(128) char smem[];
    const uint32_t sb = s2u(smem);
    const uint32_t sQH = sb, sQL = sb + AQ_B;
    const int tid = threadIdx.x, wid = tid >> 5, lane = tid & 31;
    const int bh = blockIdx.y;
    const int qi = 15 - (int)blockIdx.x;       // heavy tiles first
    const int q0 = qi * AQT;
    const int nkt = 2 * qi + 2;

    const __nv_bfloat16* qh = g_qh + (size_t)bh * Ss * HD;
    const __nv_bfloat16* ql = g_ql + (size_t)bh * Ss * HD;
    const __nv_bfloat16* kh = g_kh + (size_t)bh * Ss * HD;
    const __nv_bfloat16* kl = g_kl + (size_t)bh * Ss * HD;
    const __nv_bfloat16* vh = g_vh + (size_t)bh * Ss * HD;
    const __nv_bfloat16* vl = g_vl + (size_t)bh * Ss * HD;

    // Q hi/lo -> smem (joins first commit group)
    #pragma unroll
    for (int v = 0; v < 4; v++) {
        int id = tid + v * 256;           // 0..1023
        int row = id >> 3, c = id & 7;
        cpasync16(sQH + swz128(row, c), qh + (size_t)(q0 + row) * HD + c * 8);
        cpasync16(sQL + swz128(row, c), ql + (size_t)(q0 + row) * HD + c * 8);
    }

    auto load_kv = [&](int stage, int kt) {
        const int k0 = kt * AKT;
        uint32_t base = sb + 2 * AQ_B + stage * ASTAGE_B;
        #pragma unroll
        for (int v = 0; v < 2; v++) {
            int id = tid + v * 256;       // 0..511
            int row = id >> 3, c = id & 7;
            uint32_t so = swz128(row, c);
            cpasync16(base + so,            kh + (size_t)(k0 + row) * HD + c * 8);
            cpasync16(base + AT_B + so,     kl + (size_t)(k0 + row) * HD + c * 8);
            cpasync16(base + 2 * AT_B + so, vh + (size_t)(k0 + row) * HD + c * 8);
            cpasync16(base + 3 * AT_B + so, vl + (size_t)(k0 + row) * HD + c * 8);
        }
        cpcommit();
    };

    load_kv(0, 0);

    float oacc[8][4];
    #pragma unroll
    for (int j = 0; j < 8; j++)
        #pragma unroll
        for (int r = 0; r < 4; r++) oacc[j][r] = 0.f;
    float m0 = -1e30f, m1 = -1e30f, l0 = 0.f, l1 = 0.f;

    const int g = lane >> 2, t2 = (lane & 3) * 2;
    const int a_row = wid * 16 + (lane & 15);
    const int a_cb  = lane >> 4;
    const int b_j   = lane >> 3;
    const int b_row = ((b_j >> 1) << 3) + (lane & 7);     // K (non-trans)
    const int b_cb  = b_j & 1;
    const int vb_row = ((b_j & 1) << 3) + (lane & 7);     // V (trans): key within 16
    const int vb_ch  = b_j >> 1;                          // hd octet
    const int wrow_max = q0 + wid * 16 + 15;
    const int row0g = q0 + wid * 16 + g;

    for (int kt = 0; kt < nkt; kt++) {
        const int s = kt & 1;
        if (kt + 1 < nkt) { load_kv(1 - s, kt + 1); cpwait<1>(); }
        else              { cpwait<0>(); }
        __syncthreads();

        const int k0 = kt * AKT;
        const uint32_t bKH = sb + 2 * AQ_B + s * ASTAGE_B;
        const uint32_t bKL = bKH + AT_B;
        const uint32_t bVH = bKH + 2 * AT_B;
        const uint32_t bVL = bKH + 3 * AT_B;

        if (k0 <= wrow_max) {
            // S = Q K^T (split 3-term)
            float sacc[8][4];
            #pragma unroll
            for (int j = 0; j < 8; j++)
                #pragma unroll
                for (int r = 0; r < 4; r++) sacc[j][r] = 0.f;

            #pragma unroll
            for (int ks = 0; ks < 4; ks++) {
                uint32_t aH[4], aL[4];
                const uint32_t aoff = swz128(a_row, ks * 2 + a_cb);
                ldsm4(aH, sQH + aoff);
                ldsm4(aL, sQL + aoff);
                #pragma unroll
                for (int nt16 = 0; nt16 < 4; nt16++) {
                    const uint32_t boff = swz128(nt16 * 16 + b_row, ks * 2 + b_cb);
                    uint32_t bH[4], bL[4];
                    ldsm4(bH, bKH + boff);
                    ldsm4(bL, bKL + boff);
                    #pragma unroll
                    for (int i2 = 0; i2 < 2; i2++) {
                        float* c = sacc[nt16 * 2 + i2];
                        mma16816(c, aH, &bH[i2 * 2]);
                        mma16816(c, aH, &bL[i2 * 2]);
                        mma16816(c, aL, &bH[i2 * 2]);
                    }
                }
            }

            // scale + causal mask (diagonal tiles only)
            const bool dm = (kt >= 2 * qi);
            #pragma unroll
            for (int nt = 0; nt < 8; nt++) {
                #pragma unroll
                for (int c = 0; c < 4; c++) {
                    float val = sacc[nt][c] * 0.125f;
                    if (dm) {
                        int row = row0g + ((c >> 1) << 3);
                        int key = k0 + nt * 8 + t2 + (c & 1);
                        if (key > row) val = -1e30f;
                    }
                    sacc[nt][c] = val;
                }
            }

            // online softmax (rows g and g+8)
            float rm0 = -1e30f, rm1 = -1e30f;
            #pragma unroll
            for (int nt = 0; nt < 8; nt++) {
                rm0 = fmaxf(rm0, fmaxf(sacc[nt][0], sacc[nt][1]));
                rm1 = fmaxf(rm1, fmaxf(sacc[nt][2], sacc[nt][3]));
            }
            rm0 = fmaxf(rm0, __shfl_xor_sync(0xffffffffu, rm0, 1));
            rm0 = fmaxf(rm0, __shfl_xor_sync(0xffffffffu, rm0, 2));
            rm1 = fmaxf(rm1, __shfl_xor_sync(0xffffffffu, rm1, 1));
            rm1 = fmaxf(rm1, __shfl_xor_sync(0xffffffffu, rm1, 2));
            const float mn0 = fmaxf(m0, rm0), mn1 = fmaxf(m1, rm1);
            const float al0 = __expf(m0 - mn0), al1 = __expf(m1 - mn1);
            m0 = mn0; m1 = mn1;
            float rs0 = 0.f, rs1 = 0.f;
            #pragma unroll
            for (int nt = 0; nt < 8; nt++) {
                float p0 = __expf(sacc[nt][0] - mn0);
                float p1 = __expf(sacc[nt][1] - mn0);
                float p2 = __expf(sacc[nt][2] - mn1);
                float p3 = __expf(sacc[nt][3] - mn1);
                sacc[nt][0] = p0; sacc[nt][1] = p1;
                sacc[nt][2] = p2; sacc[nt][3] = p3;
                rs0 += p0 + p1; rs1 += p2 + p3;
            }
            rs0 += __shfl_xor_sync(0xffffffffu, rs0, 1);
            rs0 += __shfl_xor_sync(0xffffffffu, rs0, 2);
            rs1 += __shfl_xor_sync(0xffffffffu, rs1, 1);
            rs1 += __shfl_xor_sync(0xffffffffu, rs1, 2);
            l0 = l0 * al0 + rs0;
            l1 = l1 * al1 + rs1;
            #pragma unroll
            for (int nt = 0; nt < 8; nt++) {
                oacc[nt][0] *= al0; oacc[nt][1] *= al0;
                oacc[nt][2] *= al1; oacc[nt][3] *= al1;
            }

            // O += P V  (P split hi/lo; V split hi/lo; 3-term)
            #pragma unroll
            for (int ks2 = 0; ks2 < 4; ks2++) {
                uint32_t aP[4], aPl[4];
                #pragma unroll
                for (int half = 0; half < 2; half++) {        // n8 tile 2ks2+half
                    const int nt = 2 * ks2 + half;
                    __nv_bfloat16 h00 = __float2bfloat16(sacc[nt][0]);
                    __nv_bfloat16 h01 = __float2bfloat16(sacc[nt][1]);
                    __nv_bfloat16 h10 = __float2bfloat16(sacc[nt][2]);
                    __nv_bfloat16 h11 = __float2bfloat16(sacc[nt][3]);
                    aP[half * 2 + 0] = packbf(h00, h01);      // row g
                    aP[half * 2 + 1] = packbf(h10, h11);      // row g+8
                    __nv_bfloat16 e00 = __float2bfloat16(sacc[nt][0] - __bfloat162float(h00));
                    __nv_bfloat16 e01 = __float2bfloat16(sacc[nt][1] - __bfloat162float(h01));
                    __nv_bfloat16 e10 = __float2bfloat16(sacc[nt][2] - __bfloat162float(h10));
                    __nv_bfloat16 e11 = __float2bfloat16(sacc[nt][3] - __bfloat162float(h11));
                    aPl[half * 2 + 0] = packbf(e00, e01);
                    aPl[half * 2 + 1] = packbf(e10, e11);
                }
                #pragma unroll
                for (int nt16 = 0; nt16 < 4; nt16++) {        // hd 16-col groups
                    const uint32_t voff =
                        swz128(ks2 * 16 + vb_row, nt16 * 2 + vb_ch);
                    uint32_t vH[4], vL[4];
                    ldsm4t(vH, bVH + voff);
                    ldsm4t(vL, bVL + voff);
                    #pragma unroll
                    for (int i2 = 0; i2 < 2; i2++) {
                        float* c = oacc[nt16 * 2 + i2];
                        mma16816(c, aP, &vH[i2 * 2]);
                        mma16816(c, aP, &vL[i2 * 2]);
                        mma16816(c, aPl, &vH[i2 * 2]);
                    }
                }
            }
        }
        __syncthreads();
    }

    // Epilogue: normalize, write bf16 hi/lo into g_oh/g_ol [B,S,D]
    const int b = bh >> 4, h = bh & 15;
    const float inv0 = 1.f / l0, inv1 = 1.f / l1;
    const int row0 = q0 + wid * 16 + g;
    #pragma unroll
    for (int nt = 0; nt < 8; nt++) {
        const int col = h * HD + nt * 8 + t2;
        #pragma unroll
        for (int rh = 0; rh < 2; rh++) {
            const float inv = rh ? inv1 : inv0;
            const int row = row0 + rh * 8;
            float vx = oacc[nt][rh * 2 + 0] * inv;
            float vy = oacc[nt][rh * 2 + 1] * inv;
            __nv_bfloat16 hx = __float2bfloat16(vx);
            __nv_bfloat16 hy = __float2bfloat16(vy);
            __nv_bfloat16 lx = __float2bfloat16(vx - __bfloat162float(hx));
            __nv_bfloat16 ly = __float2bfloat16(vy - __bfloat162float(hy));
            size_t idx = (size_t)(b * Ss + row) * Dd + col;
            *(__nv_bfloat162*)&g_oh[idx] = __halves2bfloat162(hx, hy);
            *(__nv_bfloat162*)&g_ol[idx] = __halves2bfloat162(lx, ly);
        }
    }
}

// ---------------------------------------------------------------------------
// Launch — only harness pointers cross the host/device boundary
// ---------------------------------------------------------------------------
extern "C" void kernel_launch(void* const* d_in, const int* in_sizes, int n_in,
                              void* d_out, int out_size)
{
    const float* x  = (const float*)d_in[0];
    const float* Wq = (const float*)d_in[1];
    const float* bq = (const float*)d_in[2];
    const float* Wk = (const float*)d_in[3];
    const float* bk = (const float*)d_in[4];
    const float* Wv = (const float*)d_in[5];
    const float* bv = (const float*)d_in[6];
    const float* Wp = (const float*)d_in[7];
    const float* bp = (const float*)d_in[8];
    float* out = (float*)d_out;

    cudaFuncSetAttribute(gemm_bf16x3<0>,
                         cudaFuncAttributeMaxDynamicSharedMemorySize, GEMM_SMEM);
    cudaFuncSetAttribute(gemm_bf16x3<1>,
                         cudaFuncAttributeMaxDynamicSharedMemorySize, GEMM_SMEM);
    cudaFuncSetAttribute(attn_mma,
                         cudaFuncAttributeMaxDynamicSharedMemorySize, ATT_SMEM);

    // Conversions
    const int n4 = Mtot * Dd / 4;
    k_conv_x<<<(n4 + 255) / 256, 256>>>(x, n4);
    k_conv_wqkv<<<dim3(16, 16, 3), 256>>>(Wq, Wk, Wv);
    k_conv_wp<<<dim3(16, 16), 256>>>(Wp);
    k_bias<<<12, 256>>>(bq, bk, bv);

    // QKV projection (q/k/v all written hi/lo into [B,H,S,HD])
    gemm_bf16x3<1><<<dim3(24, 64), 256, GEMM_SMEM>>>(nullptr, nullptr);

    // Attention (mma.sync, split precision, trans-ldmatrix V)
    attn_mma<<<dim3(16, 64), 256, ATT_SMEM>>>();

    // Output projection
    gemm_bf16x3<0><<<dim3(8, 64), 256, GEMM_SMEM>>>(bp, out);
}

// round 9
// speedup vs baseline: 3.5746x; 1.0748x over previous
#include <cuda_runtime.h>
#include <cuda_bf16.h>
#include <cstdint>

// ---------------------------------------------------------------------------
// Problem constants
// ---------------------------------------------------------------------------
constexpr int Bc = 4;
constexpr int Ss = 2048;
constexpr int Dd = 1024;
constexpr int Hh = 16;
constexpr int HD = 64;
constexpr int Mtot = Bc * Ss;          // 8192
constexpr int Nqkv = 3 * Dd;           // 3072

// ---------------------------------------------------------------------------
// Scratch (device globals — referenced ONLY from device code)
// ---------------------------------------------------------------------------
__device__ __nv_bfloat16 g_qh[(size_t)Bc * Hh * Ss * HD];  // [B,H,S,HD]
__device__ __nv_bfloat16 g_ql[(size_t)Bc * Hh * Ss * HD];
__device__ __nv_bfloat16 g_kh[(size_t)Bc * Hh * Ss * HD];
__device__ __nv_bfloat16 g_kl[(size_t)Bc * Hh * Ss * HD];
__device__ __nv_bfloat16 g_vh[(size_t)Bc * Hh * Ss * HD];  // [B,H,S,HD] (same as K)
__device__ __nv_bfloat16 g_vl[(size_t)Bc * Hh * Ss * HD];

__device__ __nv_bfloat16 g_xh[(size_t)Mtot * Dd];
__device__ __nv_bfloat16 g_xl[(size_t)Mtot * Dd];
__device__ __nv_bfloat16 g_oh[(size_t)Mtot * Dd];          // attention out hi/lo
__device__ __nv_bfloat16 g_ol[(size_t)Mtot * Dd];
__device__ __nv_bfloat16 g_wth[(size_t)Nqkv * Dd];         // [N=3072][K=1024] (W^T)
__device__ __nv_bfloat16 g_wtl[(size_t)Nqkv * Dd];
__device__ __nv_bfloat16 g_wph[(size_t)Dd * Dd];           // [N=1024][K=1024] (Wp^T)
__device__ __nv_bfloat16 g_wpl[(size_t)Dd * Dd];
__device__ float g_bias[Nqkv];

// ---------------------------------------------------------------------------
// PTX helpers (baseline ISA only — assembles at .target sm_100)
// ---------------------------------------------------------------------------
__device__ __forceinline__ uint32_t s2u(const void* p) {
    uint32_t a;
    asm("{ .reg .u64 t; cvta.to.shared.u64 t, %1; cvt.u32.u64 %0, t; }"
        : "=r"(a) : "l"(p));
    return a;
}
__device__ __forceinline__ void cpasync16(uint32_t dst, const void* src) {
    asm volatile("cp.async.cg.shared.global [%0], [%1], 16;"
                 :: "r"(dst), "l"(src) : "memory");
}
__device__ __forceinline__ void cpcommit() {
    asm volatile("cp.async.commit_group;" ::: "memory");
}
template<int N> __device__ __forceinline__ void cpwait() {
    asm volatile("cp.async.wait_group %0;" :: "n"(N) : "memory");
}
__device__ __forceinline__ void ldsm4(uint32_t* r, uint32_t addr) {
    asm volatile("ldmatrix.sync.aligned.m8n8.x4.shared.b16 {%0,%1,%2,%3}, [%4];"
                 : "=r"(r[0]), "=r"(r[1]), "=r"(r[2]), "=r"(r[3]) : "r"(addr));
}
__device__ __forceinline__ void ldsm4t(uint32_t* r, uint32_t addr) {
    asm volatile("ldmatrix.sync.aligned.m8n8.x4.trans.shared.b16 {%0,%1,%2,%3}, [%4];"
                 : "=r"(r[0]), "=r"(r[1]), "=r"(r[2]), "=r"(r[3]) : "r"(addr));
}
__device__ __forceinline__ void mma16816(float* c, const uint32_t* a, const uint32_t* b) {
    asm volatile("mma.sync.aligned.m16n8k16.row.col.f32.bf16.bf16.f32 "
                 "{%0,%1,%2,%3}, {%4,%5,%6,%7}, {%8,%9}, {%0,%1,%2,%3};"
                 : "+f"(c[0]), "+f"(c[1]), "+f"(c[2]), "+f"(c[3])
                 : "r"(a[0]), "r"(a[1]), "r"(a[2]), "r"(a[3]),
                   "r"(b[0]), "r"(b[1]));
}
__device__ __forceinline__ uint32_t packbf(__nv_bfloat16 x, __nv_bfloat16 y) {
    __nv_bfloat162 t = __halves2bfloat162(x, y);
    return *(uint32_t*)&t;
}

// ---------------------------------------------------------------------------
// Conversion kernels
// ---------------------------------------------------------------------------
__global__ void k_conv_x(const float* __restrict__ src, int n4)
{
    int i = blockIdx.x * blockDim.x + threadIdx.x;
    if (i >= n4) return;
    float4 v = ((const float4*)src)[i];
    __nv_bfloat16 h0 = __float2bfloat16(v.x), h1 = __float2bfloat16(v.y);
    __nv_bfloat16 h2 = __float2bfloat16(v.z), h3 = __float2bfloat16(v.w);
    __nv_bfloat16 l0 = __float2bfloat16(v.x - __bfloat162float(h0));
    __nv_bfloat16 l1 = __float2bfloat16(v.y - __bfloat162float(h1));
    __nv_bfloat16 l2 = __float2bfloat16(v.z - __bfloat162float(h2));
    __nv_bfloat16 l3 = __float2bfloat16(v.w - __bfloat162float(h3));
    ((__nv_bfloat162*)g_xh)[2 * i]     = __halves2bfloat162(h0, h1);
    ((__nv_bfloat162*)g_xh)[2 * i + 1] = __halves2bfloat162(h2, h3);
    ((__nv_bfloat162*)g_xl)[2 * i]     = __halves2bfloat162(l0, l1);
    ((__nv_bfloat162*)g_xl)[2 * i + 1] = __halves2bfloat162(l2, l3);
}

// W[h][d][e] (per part) -> g_wth/g_wtl[(p,h,e)][d]  (transpose into K-major)
__global__ void k_conv_wqkv(const float* __restrict__ Wq,
                            const float* __restrict__ Wk,
                            const float* __restrict__ Wv)
{
    __shared__ float sm[64 * 65];
    const int d0 = blockIdx.x * 64, h = blockIdx.y, p = blockIdx.z;
    const float* W = (p == 0) ? Wq : (p == 1) ? Wk : Wv;
    const int tid = threadIdx.x;
    #pragma unroll
    for (int t = 0; t < 16; t++) {
        int idx = tid + t * 256;
        int r = idx >> 6, e = idx & 63;
        sm[r * 65 + e] = W[((size_t)h * Dd + d0 + r) * HD + e];
    }
    __syncthreads();
    #pragma unroll
    for (int t = 0; t < 16; t++) {
        int idx = tid + t * 256;
        int e = idx >> 6, r = idx & 63;
        float v = sm[r * 65 + e];
        __nv_bfloat16 hi = __float2bfloat16(v);
        __nv_bfloat16 lo = __float2bfloat16(v - __bfloat162float(hi));
        size_t n = (size_t)p * 1024 + h * 64 + e;
        g_wth[n * Dd + d0 + r] = hi;
        g_wtl[n * Dd + d0 + r] = lo;
    }
}

// Wp[k][n] -> g_wph/g_wpl[n][k]
__global__ void k_conv_wp(const float* __restrict__ Wp)
{
    __shared__ float sm[64 * 65];
    const int n0 = blockIdx.x * 64, k0 = blockIdx.y * 64;
    const int tid = threadIdx.x;
    #pragma unroll
    for (int t = 0; t < 16; t++) {
        int idx = tid + t * 256;
        int r = idx >> 6, e = idx & 63;
        sm[r * 65 + e] = Wp[(size_t)(k0 + r) * Dd + n0 + e];
    }
    __syncthreads();
    #pragma unroll
    for (int t = 0; t < 16; t++) {
        int idx = tid + t * 256;
        int e = idx >> 6, r = idx & 63;
        float v = sm[r * 65 + e];
        __nv_bfloat16 hi = __float2bfloat16(v);
        __nv_bfloat16 lo = __float2bfloat16(v - __bfloat162float(hi));
        size_t n = (size_t)(n0 + e);
        g_wph[n * Dd + k0 + r] = hi;
        g_wpl[n * Dd + k0 + r] = lo;
    }
}

__global__ void k_bias(const float* __restrict__ bq, const float* __restrict__ bk,
                       const float* __restrict__ bv)
{
    int i = blockIdx.x * 256 + threadIdx.x;
    if (i < Nqkv)
        g_bias[i] = (i < 1024) ? bq[i] : (i < 2048) ? bk[i - 1024] : bv[i - 2048];
}

// ---------------------------------------------------------------------------
// mma.sync bf16 split-precision GEMM: D fp32 += aH*bH + aH*bL + aL*bH
// CTA tile 128x128, BK=32, 128 threads = 4 warps (2m x 2n), warp tile 64x64.
//   MODE 0 (proj): A=g_oh/g_ol, B=g_wph/g_wpl, bias=param, out=param (fp32)
//   MODE 1 (qkv):  A=g_xh/g_xl, B=g_wth/g_wtl, bias=g_bias,
//                  out = bf16 hi/lo into g_{q,k,v}{h,l} [B,H,S,HD]
// ---------------------------------------------------------------------------
constexpr int GK = 1024;
constexpr int BK = 32;
constexpr int NCHUNK = GK / BK;                 // 32
constexpr int TILE_B = 128 * BK * 2;            // 8192
constexpr int STAGE_B = 4 * TILE_B;             // 32768
constexpr int GEMM_SMEM = 2 * STAGE_B;          // 65536

__device__ __forceinline__ uint32_t tswz(int row, int c) {
    return (uint32_t)(row * 64 + ((c ^ (row & 3)) << 4));
}

template<int MODE>
__global__ __launch_bounds__(128)
void gemm_bf16x3(const float* __restrict__ bias_p, float* __restrict__ out)
{
    const __nv_bfloat16* Ah = (MODE == 0) ? g_oh : g_xh;
    const __nv_bfloat16* Al = (MODE == 0) ? g_ol : g_xl;
    const __nv_bfloat16* Bh = (MODE == 0) ? g_wph : g_wth;
    const __nv_bfloat16* Bl = (MODE == 0) ? g_wpl : g_wtl;
    const float* bias = (MODE == 0) ? bias_p : g_bias;

    extern __shared__ __align__(128) char smem[];
    const uint32_t sb = s2u(smem);
    const int tid = threadIdx.x;
    const int wid = tid >> 5, lane = tid & 31;
    const int warp_m = wid & 1;                 // m offset 64*warp_m
    const int warp_n = wid >> 1;                // n offset 64*warp_n
    const int m0 = blockIdx.y * 128, n0 = blockIdx.x * 128;

    float acc[4][8][4];                         // [mt(16 rows)][n8][frag]
    #pragma unroll
    for (int i = 0; i < 4; i++)
        #pragma unroll
        for (int j = 0; j < 8; j++)
            #pragma unroll
            for (int r = 0; r < 4; r++) acc[i][j][r] = 0.f;

    auto load_chunk = [&](int stage, int kc) {
        uint32_t sbase = sb + stage * STAGE_B;
        #pragma unroll
        for (int t4 = 0; t4 < 4; t4++) {
            const __nv_bfloat16* base =
                (t4 == 0) ? Ah : (t4 == 1) ? Al : (t4 == 2) ? Bh : Bl;
            const int r0 = (t4 < 2) ? m0 : n0;
            const uint32_t tbase = sbase + t4 * TILE_B;
            #pragma unroll
            for (int v = 0; v < 4; v++) {
                int id = tid + v * 128;          // 0..511
                int row = id >> 2, c = id & 3;   // 128 rows x 4 x 16B
                const void* src = base + (size_t)(r0 + row) * GK + kc * BK + c * 8;
                cpasync16(tbase + tswz(row, c), src);
            }
        }
        cpcommit();
    };

    const int a_row = warp_m * 64 + (lane & 15);       // + mt*16
    const int a_cb  = lane >> 4;
    const int b_j   = lane >> 3;
    const int b_row = warp_n * 64 + ((b_j >> 1) << 3) + (lane & 7);  // + np*16
    const int b_cb  = b_j & 1;

    load_chunk(0, 0);

    for (int i = 0; i < NCHUNK; i++) {
        const int s = i & 1;
        if (i + 1 < NCHUNK) {
            load_chunk(1 - s, i + 1);
            cpwait<1>();
        } else {
            cpwait<0>();
        }
        __syncthreads();

        const uint32_t tAh = sb + s * STAGE_B;
        const uint32_t tAl = tAh + TILE_B;
        const uint32_t tBh = tAh + 2 * TILE_B;
        const uint32_t tBl = tAh + 3 * TILE_B;

        #pragma unroll
        for (int ks = 0; ks < 2; ks++) {
            uint32_t ah[4][4], al[4][4];
            #pragma unroll
            for (int mt = 0; mt < 4; mt++) {
                const uint32_t off = tswz(a_row + mt * 16, ks * 2 + a_cb);
                ldsm4(ah[mt], tAh + off);
                ldsm4(al[mt], tAl + off);
            }
            #pragma unroll
            for (int np = 0; np < 4; np++) {
                const uint32_t off = tswz(b_row + np * 16, ks * 2 + b_cb);
                uint32_t bh[4], bl[4];
                ldsm4(bh, tBh + off);
                ldsm4(bl, tBl + off);
                #pragma unroll
                for (int mt = 0; mt < 4; mt++) {
                    #pragma unroll
                    for (int nt = 0; nt < 2; nt++) {
                        float* c = acc[mt][np * 2 + nt];
                        mma16816(c, ah[mt], &bh[nt * 2]);
                        mma16816(c, ah[mt], &bl[nt * 2]);
                        mma16816(c, al[mt], &bh[nt * 2]);
                    }
                }
            }
        }
        __syncthreads();
    }

    const int g = lane >> 2, t2 = (lane & 3) * 2;
    #pragma unroll
    for (int mt = 0; mt < 4; mt++) {
        #pragma unroll
        for (int nt = 0; nt < 8; nt++) {
            const int ncol = n0 + warp_n * 64 + nt * 8 + t2;
            #pragma unroll
            for (int rh = 0; rh < 2; rh++) {
                const int m = m0 + warp_m * 64 + mt * 16 + g + rh * 8;
                float vx = acc[mt][nt][rh * 2 + 0] + bias[ncol];
                float vy = acc[mt][nt][rh * 2 + 1] + bias[ncol + 1];
                if (MODE == 0) {
                    float2 v; v.x = vx; v.y = vy;
                    *(float2*)&out[(size_t)m * Dd + ncol] = v;
                } else {
                    const int part = ncol >> 10;
                    const int nn = ncol & 1023;
                    const int h = nn >> 6, e = nn & 63;
                    const int b = m >> 11, s_ = m & 2047;
                    __nv_bfloat16 hx = __float2bfloat16(vx);
                    __nv_bfloat16 hy = __float2bfloat16(vy);
                    __nv_bfloat16 lx = __float2bfloat16(vx - __bfloat162float(hx));
                    __nv_bfloat16 ly = __float2bfloat16(vy - __bfloat162float(hy));
                    __nv_bfloat16* dh = (part == 0) ? g_qh : (part == 1) ? g_kh : g_vh;
                    __nv_bfloat16* dl = (part == 0) ? g_ql : (part == 1) ? g_kl : g_vl;
                    size_t idx = ((size_t)(b * Hh + h) * Ss + s_) * HD + e;
                    *(__nv_bfloat162*)&dh[idx] = __halves2bfloat162(hx, hy);
                    *(__nv_bfloat162*)&dl[idx] = __halves2bfloat162(lx, ly);
                }
            }
        }
    }
}

// ---------------------------------------------------------------------------
// Flash attention on mma.sync, split-precision (3-term) QK^T and PV.
// (unchanged from R7 — validated)
// ---------------------------------------------------------------------------
constexpr int AQT = 128, AKT = 64;
constexpr int AQ_B = 128 * 128;
constexpr int AT_B = 64 * 128;
constexpr int ASTAGE_B = 4 * AT_B;
constexpr int ATT_SMEM = 2 * AQ_B + 2 * ASTAGE_B;   // 98304

__device__ __forceinline__ uint32_t swz128(int row, int c) {
    return (uint32_t)(row * 128 + ((c ^ (row & 7)) << 4));
}

__global__ __launch_bounds__(256) void attn_mma()
{
    extern __shared__ __align__(128) char smem[];
    const uint32_t sb = s2u(smem);
    const uint32_t sQH = sb, sQL = sb + AQ_B;
    const int tid = threadIdx.x, wid = tid >> 5, lane = tid & 31;
    const int bh = blockIdx.y;
    const int qi = 15 - (int)blockIdx.x;       // heavy tiles first
    const int q0 = qi * AQT;
    const int nkt = 2 * qi + 2;

    const __nv_bfloat16* qh = g_qh + (size_t)bh * Ss * HD;
    const __nv_bfloat16* ql = g_ql + (size_t)bh * Ss * HD;
    const __nv_bfloat16* kh = g_kh + (size_t)bh * Ss * HD;
    const __nv_bfloat16* kl = g_kl + (size_t)bh * Ss * HD;
    const __nv_bfloat16* vh = g_vh + (size_t)bh * Ss * HD;
    const __nv_bfloat16* vl = g_vl + (size_t)bh * Ss * HD;

    #pragma unroll
    for (int v = 0; v < 4; v++) {
        int id = tid + v * 256;
        int row = id >> 3, c = id & 7;
        cpasync16(sQH + swz128(row, c), qh + (size_t)(q0 + row) * HD + c * 8);
        cpasync16(sQL + swz128(row, c), ql + (size_t)(q0 + row) * HD + c * 8);
    }

    auto load_kv = [&](int stage, int kt) {
        const int k0 = kt * AKT;
        uint32_t base = sb + 2 * AQ_B + stage * ASTAGE_B;
        #pragma unroll
        for (int v = 0; v < 2; v++) {
            int id = tid + v * 256;
            int row = id >> 3, c = id & 7;
            uint32_t so = swz128(row, c);
            cpasync16(base + so,            kh + (size_t)(k0 + row) * HD + c * 8);
            cpasync16(base + AT_B + so,     kl + (size_t)(k0 + row) * HD + c * 8);
            cpasync16(base + 2 * AT_B + so, vh + (size_t)(k0 + row) * HD + c * 8);
            cpasync16(base + 3 * AT_B + so, vl + (size_t)(k0 + row) * HD + c * 8);
        }
        cpcommit();
    };

    load_kv(0, 0);

    float oacc[8][4];
    #pragma unroll
    for (int j = 0; j < 8; j++)
        #pragma unroll
        for (int r = 0; r < 4; r++) oacc[j][r] = 0.f;
    float m0 = -1e30f, m1 = -1e30f, l0 = 0.f, l1 = 0.f;

    const int g = lane >> 2, t2 = (lane & 3) * 2;
    const int a_row = wid * 16 + (lane & 15);
    const int a_cb  = lane >> 4;
    const int b_j   = lane >> 3;
    const int b_row = ((b_j >> 1) << 3) + (lane & 7);
    const int b_cb  = b_j & 1;
    const int vb_row = ((b_j & 1) << 3) + (lane & 7);
    const int vb_ch  = b_j >> 1;
    const int wrow_max = q0 + wid * 16 + 15;
    const int row0g = q0 + wid * 16 + g;

    for (int kt = 0; kt < nkt; kt++) {
        const int s = kt & 1;
        if (kt + 1 < nkt) { load_kv(1 - s, kt + 1); cpwait<1>(); }
        else              { cpwait<0>(); }
        __syncthreads();

        const int k0 = kt * AKT;
        const uint32_t bKH = sb + 2 * AQ_B + s * ASTAGE_B;
        const uint32_t bKL = bKH + AT_B;
        const uint32_t bVH = bKH + 2 * AT_B;
        const uint32_t bVL = bKH + 3 * AT_B;

        if (k0 <= wrow_max) {
            float sacc[8][4];
            #pragma unroll
            for (int j = 0; j < 8; j++)
                #pragma unroll
                for (int r = 0; r < 4; r++) sacc[j][r] = 0.f;

            #pragma unroll
            for (int ks = 0; ks < 4; ks++) {
                uint32_t aH[4], aL[4];
                const uint32_t aoff = swz128(a_row, ks * 2 + a_cb);
                ldsm4(aH, sQH + aoff);
                ldsm4(aL, sQL + aoff);
                #pragma unroll
                for (int nt16 = 0; nt16 < 4; nt16++) {
                    const uint32_t boff = swz128(nt16 * 16 + b_row, ks * 2 + b_cb);
                    uint32_t bH[4], bL[4];
                    ldsm4(bH, bKH + boff);
                    ldsm4(bL, bKL + boff);
                    #pragma unroll
                    for (int i2 = 0; i2 < 2; i2++) {
                        float* c = sacc[nt16 * 2 + i2];
                        mma16816(c, aH, &bH[i2 * 2]);
                        mma16816(c, aH, &bL[i2 * 2]);
                        mma16816(c, aL, &bH[i2 * 2]);
                    }
                }
            }

            const bool dm = (kt >= 2 * qi);
            #pragma unroll
            for (int nt = 0; nt < 8; nt++) {
                #pragma unroll
                for (int c = 0; c < 4; c++) {
                    float val = sacc[nt][c] * 0.125f;
                    if (dm) {
                        int row = row0g + ((c >> 1) << 3);
                        int key = k0 + nt * 8 + t2 + (c & 1);
                        if (key > row) val = -1e30f;
                    }
                    sacc[nt][c] = val;
                }
            }

            float rm0 = -1e30f, rm1 = -1e30f;
            #pragma unroll
            for (int nt = 0; nt < 8; nt++) {
                rm0 = fmaxf(rm0, fmaxf(sacc[nt][0], sacc[nt][1]));
                rm1 = fmaxf(rm1, fmaxf(sacc[nt][2], sacc[nt][3]));
            }
            rm0 = fmaxf(rm0, __shfl_xor_sync(0xffffffffu, rm0, 1));
            rm0 = fmaxf(rm0, __shfl_xor_sync(0xffffffffu, rm0, 2));
            rm1 = fmaxf(rm1, __shfl_xor_sync(0xffffffffu, rm1, 1));
            rm1 = fmaxf(rm1, __shfl_xor_sync(0xffffffffu, rm1, 2));
            const float mn0 = fmaxf(m0, rm0), mn1 = fmaxf(m1, rm1);
            const float al0 = __expf(m0 - mn0), al1 = __expf(m1 - mn1);
            m0 = mn0; m1 = mn1;
            float rs0 = 0.f, rs1 = 0.f;
            #pragma unroll
            for (int nt = 0; nt < 8; nt++) {
                float p0 = __expf(sacc[nt][0] - mn0);
                float p1 = __expf(sacc[nt][1] - mn0);
                float p2 = __expf(sacc[nt][2] - mn1);
                float p3 = __expf(sacc[nt][3] - mn1);
                sacc[nt][0] = p0; sacc[nt][1] = p1;
                sacc[nt][2] = p2; sacc[nt][3] = p3;
                rs0 += p0 + p1; rs1 += p2 + p3;
            }
            rs0 += __shfl_xor_sync(0xffffffffu, rs0, 1);
            rs0 += __shfl_xor_sync(0xffffffffu, rs0, 2);
            rs1 += __shfl_xor_sync(0xffffffffu, rs1, 1);
            rs1 += __shfl_xor_sync(0xffffffffu, rs1, 2);
            l0 = l0 * al0 + rs0;
            l1 = l1 * al1 + rs1;
            #pragma unroll
            for (int nt = 0; nt < 8; nt++) {
                oacc[nt][0] *= al0; oacc[nt][1] *= al0;
                oacc[nt][2] *= al1; oacc[nt][3] *= al1;
            }

            #pragma unroll
            for (int ks2 = 0; ks2 < 4; ks2++) {
                uint32_t aP[4], aPl[4];
                #pragma unroll
                for (int half = 0; half < 2; half++) {
                    const int nt = 2 * ks2 + half;
                    __nv_bfloat16 h00 = __float2bfloat16(sacc[nt][0]);
                    __nv_bfloat16 h01 = __float2bfloat16(sacc[nt][1]);
                    __nv_bfloat16 h10 = __float2bfloat16(sacc[nt][2]);
                    __nv_bfloat16 h11 = __float2bfloat16(sacc[nt][3]);
                    aP[half * 2 + 0] = packbf(h00, h01);
                    aP[half * 2 + 1] = packbf(h10, h11);
                    __nv_bfloat16 e00 = __float2bfloat16(sacc[nt][0] - __bfloat162float(h00));
                    __nv_bfloat16 e01 = __float2bfloat16(sacc[nt][1] - __bfloat162float(h01));
                    __nv_bfloat16 e10 = __float2bfloat16(sacc[nt][2] - __bfloat162float(h10));
                    __nv_bfloat16 e11 = __float2bfloat16(sacc[nt][3] - __bfloat162float(h11));
                    aPl[half * 2 + 0] = packbf(e00, e01);
                    aPl[half * 2 + 1] = packbf(e10, e11);
                }
                #pragma unroll
                for (int nt16 = 0; nt16 < 4; nt16++) {
                    const uint32_t voff =
                        swz128(ks2 * 16 + vb_row, nt16 * 2 + vb_ch);
                    uint32_t vH[4], vL[4];
                    ldsm4t(vH, bVH + voff);
                    ldsm4t(vL, bVL + voff);
                    #pragma unroll
                    for (int i2 = 0; i2 < 2; i2++) {
                        float* c = oacc[nt16 * 2 + i2];
                        mma16816(c, aP, &vH[i2 * 2]);
                        mma16816(c, aP, &vL[i2 * 2]);
                        mma16816(c, aPl, &vH[i2 * 2]);
                    }
                }
            }
        }
        __syncthreads();
    }

    const int b = bh >> 4, h = bh & 15;
    const float inv0 = 1.f / l0, inv1 = 1.f / l1;
    const int row0 = q0 + wid * 16 + g;
    #pragma unroll
    for (int nt = 0; nt < 8; nt++) {
        const int col = h * HD + nt * 8 + t2;
        #pragma unroll
        for (int rh = 0; rh < 2; rh++) {
            const float inv = rh ? inv1 : inv0;
            const int row = row0 + rh * 8;
            float vx = oacc[nt][rh * 2 + 0] * inv;
            float vy = oacc[nt][rh * 2 + 1] * inv;
            __nv_bfloat16 hx = __float2bfloat16(vx);
            __nv_bfloat16 hy = __float2bfloat16(vy);
            __nv_bfloat16 lx = __float2bfloat16(vx - __bfloat162float(hx));
            __nv_bfloat16 ly = __float2bfloat16(vy - __bfloat162float(hy));
            size_t idx = (size_t)(b * Ss + row) * Dd + col;
            *(__nv_bfloat162*)&g_oh[idx] = __halves2bfloat162(hx, hy);
            *(__nv_bfloat162*)&g_ol[idx] = __halves2bfloat162(lx, ly);
        }
    }
}

// ---------------------------------------------------------------------------
// Launch — only harness pointers cross the host/device boundary
// ---------------------------------------------------------------------------
extern "C" void kernel_launch(void* const* d_in, const int* in_sizes, int n_in,
                              void* d_out, int out_size)
{
    const float* x  = (const float*)d_in[0];
    const float* Wq = (const float*)d_in[1];
    const float* bq = (const float*)d_in[2];
    const float* Wk = (const float*)d_in[3];
    const float* bk = (const float*)d_in[4];
    const float* Wv = (const float*)d_in[5];
    const float* bv = (const float*)d_in[6];
    const float* Wp = (const float*)d_in[7];
    const float* bp = (const float*)d_in[8];
    float* out = (float*)d_out;

    cudaFuncSetAttribute(gemm_bf16x3<0>,
                         cudaFuncAttributeMaxDynamicSharedMemorySize, GEMM_SMEM);
    cudaFuncSetAttribute(gemm_bf16x3<1>,
                         cudaFuncAttributeMaxDynamicSharedMemorySize, GEMM_SMEM);
    cudaFuncSetAttribute(attn_mma,
                         cudaFuncAttributeMaxDynamicSharedMemorySize, ATT_SMEM);

    // Conversions
    const int n4 = Mtot * Dd / 4;
    k_conv_x<<<(n4 + 255) / 256, 256>>>(x, n4);
    k_conv_wqkv<<<dim3(16, 16, 3), 256>>>(Wq, Wk, Wv);
    k_conv_wp<<<dim3(16, 16), 256>>>(Wp);
    k_bias<<<12, 256>>>(bq, bk, bv);

    // QKV projection (q/k/v all written hi/lo into [B,H,S,HD])
    gemm_bf16x3<1><<<dim3(24, 64), 128, GEMM_SMEM>>>(nullptr, nullptr);

    // Attention (mma.sync, split precision, trans-ldmatrix V)
    attn_mma<<<dim3(16, 64), 256, ATT_SMEM>>>();

    // Output projection
    gemm_bf16x3<0><<<dim3(8, 64), 128, GEMM_SMEM>>>(bp, out);
}

// round 10
// speedup vs baseline: 3.7161x; 1.0396x over previous
#include <cuda_runtime.h>
#include <cuda_bf16.h>
#include <cstdint>

// ---------------------------------------------------------------------------
// Problem constants
// ---------------------------------------------------------------------------
constexpr int Bc = 4;
constexpr int Ss = 2048;
constexpr int Dd = 1024;
constexpr int Hh = 16;
constexpr int HD = 64;
constexpr int Mtot = Bc * Ss;          // 8192
constexpr int Nqkv = 3 * Dd;           // 3072

// ---------------------------------------------------------------------------
// Scratch (device globals — referenced ONLY from device code)
// ---------------------------------------------------------------------------
__device__ __nv_bfloat16 g_qh[(size_t)Bc * Hh * Ss * HD];  // [B,H,S,HD]
__device__ __nv_bfloat16 g_ql[(size_t)Bc * Hh * Ss * HD];
__device__ __nv_bfloat16 g_kh[(size_t)Bc * Hh * Ss * HD];
__device__ __nv_bfloat16 g_kl[(size_t)Bc * Hh * Ss * HD];
__device__ __nv_bfloat16 g_vh[(size_t)Bc * Hh * Ss * HD];  // [B,H,S,HD] (same as K)
__device__ __nv_bfloat16 g_vl[(size_t)Bc * Hh * Ss * HD];

__device__ __nv_bfloat16 g_xh[(size_t)Mtot * Dd];
__device__ __nv_bfloat16 g_xl[(size_t)Mtot * Dd];
__device__ __nv_bfloat16 g_oh[(size_t)Mtot * Dd];          // attention out hi/lo
__device__ __nv_bfloat16 g_ol[(size_t)Mtot * Dd];
__device__ __nv_bfloat16 g_wth[(size_t)Nqkv * Dd];         // [N=3072][K=1024] (W^T)
__device__ __nv_bfloat16 g_wtl[(size_t)Nqkv * Dd];
__device__ __nv_bfloat16 g_wph[(size_t)Dd * Dd];           // [N=1024][K=1024] (Wp^T)
__device__ __nv_bfloat16 g_wpl[(size_t)Dd * Dd];
__device__ float g_bias[Nqkv];

// ---------------------------------------------------------------------------
// PTX helpers (baseline ISA only — assembles at .target sm_100)
// ---------------------------------------------------------------------------
__device__ __forceinline__ uint32_t s2u(const void* p) {
    uint32_t a;
    asm("{ .reg .u64 t; cvta.to.shared.u64 t, %1; cvt.u32.u64 %0, t; }"
        : "=r"(a) : "l"(p));
    return a;
}
__device__ __forceinline__ void cpasync16(uint32_t dst, const void* src) {
    asm volatile("cp.async.cg.shared.global [%0], [%1], 16;"
                 :: "r"(dst), "l"(src) : "memory");
}
__device__ __forceinline__ void cpcommit() {
    asm volatile("cp.async.commit_group;" ::: "memory");
}
template<int N> __device__ __forceinline__ void cpwait() {
    asm volatile("cp.async.wait_group %0;" :: "n"(N) : "memory");
}
__device__ __forceinline__ void ldsm4(uint32_t* r, uint32_t addr) {
    asm volatile("ldmatrix.sync.aligned.m8n8.x4.shared.b16 {%0,%1,%2,%3}, [%4];"
                 : "=r"(r[0]), "=r"(r[1]), "=r"(r[2]), "=r"(r[3]) : "r"(addr));
}
__device__ __forceinline__ void ldsm4t(uint32_t* r, uint32_t addr) {
    asm volatile("ldmatrix.sync.aligned.m8n8.x4.trans.shared.b16 {%0,%1,%2,%3}, [%4];"
                 : "=r"(r[0]), "=r"(r[1]), "=r"(r[2]), "=r"(r[3]) : "r"(addr));
}
__device__ __forceinline__ void mma16816(float* c, const uint32_t* a, const uint32_t* b) {
    asm volatile("mma.sync.aligned.m16n8k16.row.col.f32.bf16.bf16.f32 "
                 "{%0,%1,%2,%3}, {%4,%5,%6,%7}, {%8,%9}, {%0,%1,%2,%3};"
                 : "+f"(c[0]), "+f"(c[1]), "+f"(c[2]), "+f"(c[3])
                 : "r"(a[0]), "r"(a[1]), "r"(a[2]), "r"(a[3]),
                   "r"(b[0]), "r"(b[1]));
}
__device__ __forceinline__ uint32_t packbf(__nv_bfloat16 x, __nv_bfloat16 y) {
    __nv_bfloat162 t = __halves2bfloat162(x, y);
    return *(uint32_t*)&t;
}

// ---------------------------------------------------------------------------
// Conversion kernels
// ---------------------------------------------------------------------------
__global__ void k_conv_x(const float* __restrict__ src, int n4)
{
    int i = blockIdx.x * blockDim.x + threadIdx.x;
    if (i >= n4) return;
    float4 v = ((const float4*)src)[i];
    __nv_bfloat16 h0 = __float2bfloat16(v.x), h1 = __float2bfloat16(v.y);
    __nv_bfloat16 h2 = __float2bfloat16(v.z), h3 = __float2bfloat16(v.w);
    __nv_bfloat16 l0 = __float2bfloat16(v.x - __bfloat162float(h0));
    __nv_bfloat16 l1 = __float2bfloat16(v.y - __bfloat162float(h1));
    __nv_bfloat16 l2 = __float2bfloat16(v.z - __bfloat162float(h2));
    __nv_bfloat16 l3 = __float2bfloat16(v.w - __bfloat162float(h3));
    ((__nv_bfloat162*)g_xh)[2 * i]     = __halves2bfloat162(h0, h1);
    ((__nv_bfloat162*)g_xh)[2 * i + 1] = __halves2bfloat162(h2, h3);
    ((__nv_bfloat162*)g_xl)[2 * i]     = __halves2bfloat162(l0, l1);
    ((__nv_bfloat162*)g_xl)[2 * i + 1] = __halves2bfloat162(l2, l3);
}

// W[h][d][e] (per part) -> g_wth/g_wtl[(p,h,e)][d]  (transpose into K-major)
__global__ void k_conv_wqkv(const float* __restrict__ Wq,
                            const float* __restrict__ Wk,
                            const float* __restrict__ Wv)
{
    __shared__ float sm[64 * 65];
    const int d0 = blockIdx.x * 64, h = blockIdx.y, p = blockIdx.z;
    const float* W = (p == 0) ? Wq : (p == 1) ? Wk : Wv;
    const int tid = threadIdx.x;
    #pragma unroll
    for (int t = 0; t < 16; t++) {
        int idx = tid + t * 256;
        int r = idx >> 6, e = idx & 63;
        sm[r * 65 + e] = W[((size_t)h * Dd + d0 + r) * HD + e];
    }
    __syncthreads();
    #pragma unroll
    for (int t = 0; t < 16; t++) {
        int idx = tid + t * 256;
        int e = idx >> 6, r = idx & 63;
        float v = sm[r * 65 + e];
        __nv_bfloat16 hi = __float2bfloat16(v);
        __nv_bfloat16 lo = __float2bfloat16(v - __bfloat162float(hi));
        size_t n = (size_t)p * 1024 + h * 64 + e;
        g_wth[n * Dd + d0 + r] = hi;
        g_wtl[n * Dd + d0 + r] = lo;
    }
}

// Wp[k][n] -> g_wph/g_wpl[n][k]
__global__ void k_conv_wp(const float* __restrict__ Wp)
{
    __shared__ float sm[64 * 65];
    const int n0 = blockIdx.x * 64, k0 = blockIdx.y * 64;
    const int tid = threadIdx.x;
    #pragma unroll
    for (int t = 0; t < 16; t++) {
        int idx = tid + t * 256;
        int r = idx >> 6, e = idx & 63;
        sm[r * 65 + e] = Wp[(size_t)(k0 + r) * Dd + n0 + e];
    }
    __syncthreads();
    #pragma unroll
    for (int t = 0; t < 16; t++) {
        int idx = tid + t * 256;
        int e = idx >> 6, r = idx & 63;
        float v = sm[r * 65 + e];
        __nv_bfloat16 hi = __float2bfloat16(v);
        __nv_bfloat16 lo = __float2bfloat16(v - __bfloat162float(hi));
        size_t n = (size_t)(n0 + e);
        g_wph[n * Dd + k0 + r] = hi;
        g_wpl[n * Dd + k0 + r] = lo;
    }
}

__global__ void k_bias(const float* __restrict__ bq, const float* __restrict__ bk,
                       const float* __restrict__ bv)
{
    int i = blockIdx.x * 256 + threadIdx.x;
    if (i < Nqkv)
        g_bias[i] = (i < 1024) ? bq[i] : (i < 2048) ? bk[i - 1024] : bv[i - 2048];
}

// ---------------------------------------------------------------------------
// mma.sync bf16 split-precision GEMM (validated R9): D += aH*bH + aH*bL + aL*bH
// CTA tile 128x128, BK=32, 128 threads = 4 warps (2m x 2n), warp tile 64x64.
// ---------------------------------------------------------------------------
constexpr int GK = 1024;
constexpr int BK = 32;
constexpr int NCHUNK = GK / BK;                 // 32
constexpr int TILE_B = 128 * BK * 2;            // 8192
constexpr int STAGE_B = 4 * TILE_B;             // 32768
constexpr int GEMM_SMEM = 2 * STAGE_B;          // 65536

__device__ __forceinline__ uint32_t tswz(int row, int c) {
    return (uint32_t)(row * 64 + ((c ^ (row & 3)) << 4));
}

template<int MODE>
__global__ __launch_bounds__(128)
void gemm_bf16x3(const float* __restrict__ bias_p, float* __restrict__ out)
{
    const __nv_bfloat16* Ah = (MODE == 0) ? g_oh : g_xh;
    const __nv_bfloat16* Al = (MODE == 0) ? g_ol : g_xl;
    const __nv_bfloat16* Bh = (MODE == 0) ? g_wph : g_wth;
    const __nv_bfloat16* Bl = (MODE == 0) ? g_wpl : g_wtl;
    const float* bias = (MODE == 0) ? bias_p : g_bias;

    extern __shared__ __align__(128) char smem[];
    const uint32_t sb = s2u(smem);
    const int tid = threadIdx.x;
    const int wid = tid >> 5, lane = tid & 31;
    const int warp_m = wid & 1;
    const int warp_n = wid >> 1;
    const int m0 = blockIdx.y * 128, n0 = blockIdx.x * 128;

    float acc[4][8][4];
    #pragma unroll
    for (int i = 0; i < 4; i++)
        #pragma unroll
        for (int j = 0; j < 8; j++)
            #pragma unroll
            for (int r = 0; r < 4; r++) acc[i][j][r] = 0.f;

    auto load_chunk = [&](int stage, int kc) {
        uint32_t sbase = sb + stage * STAGE_B;
        #pragma unroll
        for (int t4 = 0; t4 < 4; t4++) {
            const __nv_bfloat16* base =
                (t4 == 0) ? Ah : (t4 == 1) ? Al : (t4 == 2) ? Bh : Bl;
            const int r0 = (t4 < 2) ? m0 : n0;
            const uint32_t tbase = sbase + t4 * TILE_B;
            #pragma unroll
            for (int v = 0; v < 4; v++) {
                int id = tid + v * 128;
                int row = id >> 2, c = id & 3;
                const void* src = base + (size_t)(r0 + row) * GK + kc * BK + c * 8;
                cpasync16(tbase + tswz(row, c), src);
            }
        }
        cpcommit();
    };

    const int a_row = warp_m * 64 + (lane & 15);
    const int a_cb  = lane >> 4;
    const int b_j   = lane >> 3;
    const int b_row = warp_n * 64 + ((b_j >> 1) << 3) + (lane & 7);
    const int b_cb  = b_j & 1;

    load_chunk(0, 0);

    for (int i = 0; i < NCHUNK; i++) {
        const int s = i & 1;
        if (i + 1 < NCHUNK) {
            load_chunk(1 - s, i + 1);
            cpwait<1>();
        } else {
            cpwait<0>();
        }
        __syncthreads();

        const uint32_t tAh = sb + s * STAGE_B;
        const uint32_t tAl = tAh + TILE_B;
        const uint32_t tBh = tAh + 2 * TILE_B;
        const uint32_t tBl = tAh + 3 * TILE_B;

        #pragma unroll
        for (int ks = 0; ks < 2; ks++) {
            uint32_t ah[4][4], al[4][4];
            #pragma unroll
            for (int mt = 0; mt < 4; mt++) {
                const uint32_t off = tswz(a_row + mt * 16, ks * 2 + a_cb);
                ldsm4(ah[mt], tAh + off);
                ldsm4(al[mt], tAl + off);
            }
            #pragma unroll
            for (int np = 0; np < 4; np++) {
                const uint32_t off = tswz(b_row + np * 16, ks * 2 + b_cb);
                uint32_t bh[4], bl[4];
                ldsm4(bh, tBh + off);
                ldsm4(bl, tBl + off);
                #pragma unroll
                for (int mt = 0; mt < 4; mt++) {
                    #pragma unroll
                    for (int nt = 0; nt < 2; nt++) {
                        float* c = acc[mt][np * 2 + nt];
                        mma16816(c, ah[mt], &bh[nt * 2]);
                        mma16816(c, ah[mt], &bl[nt * 2]);
                        mma16816(c, al[mt], &bh[nt * 2]);
                    }
                }
            }
        }
        __syncthreads();
    }

    const int g = lane >> 2, t2 = (lane & 3) * 2;
    #pragma unroll
    for (int mt = 0; mt < 4; mt++) {
        #pragma unroll
        for (int nt = 0; nt < 8; nt++) {
            const int ncol = n0 + warp_n * 64 + nt * 8 + t2;
            #pragma unroll
            for (int rh = 0; rh < 2; rh++) {
                const int m = m0 + warp_m * 64 + mt * 16 + g + rh * 8;
                float vx = acc[mt][nt][rh * 2 + 0] + bias[ncol];
                float vy = acc[mt][nt][rh * 2 + 1] + bias[ncol + 1];
                if (MODE == 0) {
                    float2 v; v.x = vx; v.y = vy;
                    *(float2*)&out[(size_t)m * Dd + ncol] = v;
                } else {
                    const int part = ncol >> 10;
                    const int nn = ncol & 1023;
                    const int h = nn >> 6, e = nn & 63;
                    const int b = m >> 11, s_ = m & 2047;
                    __nv_bfloat16 hx = __float2bfloat16(vx);
                    __nv_bfloat16 hy = __float2bfloat16(vy);
                    __nv_bfloat16 lx = __float2bfloat16(vx - __bfloat162float(hx));
                    __nv_bfloat16 ly = __float2bfloat16(vy - __bfloat162float(hy));
                    __nv_bfloat16* dh = (part == 0) ? g_qh : (part == 1) ? g_kh : g_vh;
                    __nv_bfloat16* dl = (part == 0) ? g_ql : (part == 1) ? g_kl : g_vl;
                    size_t idx = ((size_t)(b * Hh + h) * Ss + s_) * HD + e;
                    *(__nv_bfloat162*)&dh[idx] = __halves2bfloat162(hx, hy);
                    *(__nv_bfloat162*)&dl[idx] = __halves2bfloat162(lx, ly);
                }
            }
        }
    }
}

// ---------------------------------------------------------------------------
// Flash attention on mma.sync, split-precision (3-term) QK^T and PV.
// R10: 4 warps x 32 q-rows (was 8 x 16) — halves redundant K/V ldmatrix
// traffic, doubles HMMA density per warp. Same smem layout / staging.
// ---------------------------------------------------------------------------
constexpr int AQT = 128, AKT = 64;
constexpr int AQ_B = 128 * 128;
constexpr int AT_B = 64 * 128;
constexpr int ASTAGE_B = 4 * AT_B;
constexpr int ATT_SMEM = 2 * AQ_B + 2 * ASTAGE_B;   // 98304

__device__ __forceinline__ uint32_t swz128(int row, int c) {
    return (uint32_t)(row * 128 + ((c ^ (row & 7)) << 4));
}

__global__ __launch_bounds__(128) void attn_mma()
{
    extern __shared__ __align__(128) char smem[];
    const uint32_t sb = s2u(smem);
    const uint32_t sQH = sb, sQL = sb + AQ_B;
    const int tid = threadIdx.x, wid = tid >> 5, lane = tid & 31;
    const int bh = blockIdx.y;
    const int qi = 15 - (int)blockIdx.x;       // heavy tiles first
    const int q0 = qi * AQT;
    const int nkt = 2 * qi + 2;

    const __nv_bfloat16* qh = g_qh + (size_t)bh * Ss * HD;
    const __nv_bfloat16* ql = g_ql + (size_t)bh * Ss * HD;
    const __nv_bfloat16* kh = g_kh + (size_t)bh * Ss * HD;
    const __nv_bfloat16* kl = g_kl + (size_t)bh * Ss * HD;
    const __nv_bfloat16* vh = g_vh + (size_t)bh * Ss * HD;
    const __nv_bfloat16* vl = g_vl + (size_t)bh * Ss * HD;

    // Q hi/lo -> smem (joins first commit group)
    #pragma unroll
    for (int v = 0; v < 8; v++) {
        int id = tid + v * 128;           // 0..1023
        int row = id >> 3, c = id & 7;
        cpasync16(sQH + swz128(row, c), qh + (size_t)(q0 + row) * HD + c * 8);
        cpasync16(sQL + swz128(row, c), ql + (size_t)(q0 + row) * HD + c * 8);
    }

    auto load_kv = [&](int stage, int kt) {
        const int k0 = kt * AKT;
        uint32_t base = sb + 2 * AQ_B + stage * ASTAGE_B;
        #pragma unroll
        for (int v = 0; v < 4; v++) {
            int id = tid + v * 128;       // 0..511
            int row = id >> 3, c = id & 7;
            uint32_t so = swz128(row, c);
            cpasync16(base + so,            kh + (size_t)(k0 + row) * HD + c * 8);
            cpasync16(base + AT_B + so,     kl + (size_t)(k0 + row) * HD + c * 8);
            cpasync16(base + 2 * AT_B + so, vh + (size_t)(k0 + row) * HD + c * 8);
            cpasync16(base + 3 * AT_B + so, vl + (size_t)(k0 + row) * HD + c * 8);
        }
        cpcommit();
    };

    load_kv(0, 0);

    float oacc[2][8][4];                 // [mt][hd n8][frag]
    #pragma unroll
    for (int mt = 0; mt < 2; mt++)
        #pragma unroll
        for (int j = 0; j < 8; j++)
            #pragma unroll
            for (int r = 0; r < 4; r++) oacc[mt][j][r] = 0.f;
    float mm[4] = {-1e30f, -1e30f, -1e30f, -1e30f};   // [mt*2+rh]
    float ll[4] = {0.f, 0.f, 0.f, 0.f};

    const int g = lane >> 2, t2 = (lane & 3) * 2;
    const int a_row = wid * 32 + (lane & 15);          // + mt*16
    const int a_cb  = lane >> 4;
    const int b_j   = lane >> 3;
    const int b_row = ((b_j >> 1) << 3) + (lane & 7);
    const int b_cb  = b_j & 1;
    const int vb_row = ((b_j & 1) << 3) + (lane & 7);
    const int vb_ch  = b_j >> 1;
    const int wrow_max = q0 + wid * 32 + 31;
    const int row0g = q0 + wid * 32 + g;

    for (int kt = 0; kt < nkt; kt++) {
        const int s = kt & 1;
        if (kt + 1 < nkt) { load_kv(1 - s, kt + 1); cpwait<1>(); }
        else              { cpwait<0>(); }
        __syncthreads();

        const int k0 = kt * AKT;
        const uint32_t bKH = sb + 2 * AQ_B + s * ASTAGE_B;
        const uint32_t bKL = bKH + AT_B;
        const uint32_t bVH = bKH + 2 * AT_B;
        const uint32_t bVL = bKH + 3 * AT_B;

        if (k0 <= wrow_max) {
            // S = Q K^T (split 3-term), 32 rows x 64 keys
            float sacc[2][8][4];
            #pragma unroll
            for (int mt = 0; mt < 2; mt++)
                #pragma unroll
                for (int j = 0; j < 8; j++)
                    #pragma unroll
                    for (int r = 0; r < 4; r++) sacc[mt][j][r] = 0.f;

            #pragma unroll
            for (int ks = 0; ks < 4; ks++) {
                uint32_t aH[2][4], aL[2][4];
                #pragma unroll
                for (int mt = 0; mt < 2; mt++) {
                    const uint32_t aoff = swz128(a_row + mt * 16, ks * 2 + a_cb);
                    ldsm4(aH[mt], sQH + aoff);
                    ldsm4(aL[mt], sQL + aoff);
                }
                #pragma unroll
                for (int nt16 = 0; nt16 < 4; nt16++) {
                    const uint32_t boff = swz128(nt16 * 16 + b_row, ks * 2 + b_cb);
                    uint32_t bH[4], bL[4];
                    ldsm4(bH, bKH + boff);
                    ldsm4(bL, bKL + boff);
                    #pragma unroll
                    for (int mt = 0; mt < 2; mt++) {
                        #pragma unroll
                        for (int i2 = 0; i2 < 2; i2++) {
                            float* c = sacc[mt][nt16 * 2 + i2];
                            mma16816(c, aH[mt], &bH[i2 * 2]);
                            mma16816(c, aH[mt], &bL[i2 * 2]);
                            mma16816(c, aL[mt], &bH[i2 * 2]);
                        }
                    }
                }
            }

            // scale + causal mask (diagonal tiles only)
            const bool dm = (kt >= 2 * qi);
            #pragma unroll
            for (int mt = 0; mt < 2; mt++)
                #pragma unroll
                for (int nt = 0; nt < 8; nt++)
                    #pragma unroll
                    for (int c = 0; c < 4; c++) {
                        float val = sacc[mt][nt][c] * 0.125f;
                        if (dm) {
                            int row = row0g + mt * 16 + ((c >> 1) << 3);
                            int key = k0 + nt * 8 + t2 + (c & 1);
                            if (key > row) val = -1e30f;
                        }
                        sacc[mt][nt][c] = val;
                    }

            // online softmax: 4 row-states (mt x row-half)
            #pragma unroll
            for (int mt = 0; mt < 2; mt++) {
                float rm0 = -1e30f, rm1 = -1e30f;
                #pragma unroll
                for (int nt = 0; nt < 8; nt++) {
                    rm0 = fmaxf(rm0, fmaxf(sacc[mt][nt][0], sacc[mt][nt][1]));
                    rm1 = fmaxf(rm1, fmaxf(sacc[mt][nt][2], sacc[mt][nt][3]));
                }
                rm0 = fmaxf(rm0, __shfl_xor_sync(0xffffffffu, rm0, 1));
                rm0 = fmaxf(rm0, __shfl_xor_sync(0xffffffffu, rm0, 2));
                rm1 = fmaxf(rm1, __shfl_xor_sync(0xffffffffu, rm1, 1));
                rm1 = fmaxf(rm1, __shfl_xor_sync(0xffffffffu, rm1, 2));
                const float mn0 = fmaxf(mm[mt * 2 + 0], rm0);
                const float mn1 = fmaxf(mm[mt * 2 + 1], rm1);
                const float al0 = __expf(mm[mt * 2 + 0] - mn0);
                const float al1 = __expf(mm[mt * 2 + 1] - mn1);
                mm[mt * 2 + 0] = mn0; mm[mt * 2 + 1] = mn1;
                float rs0 = 0.f, rs1 = 0.f;
                #pragma unroll
                for (int nt = 0; nt < 8; nt++) {
                    float p0 = __expf(sacc[mt][nt][0] - mn0);
                    float p1 = __expf(sacc[mt][nt][1] - mn0);
                    float p2 = __expf(sacc[mt][nt][2] - mn1);
                    float p3 = __expf(sacc[mt][nt][3] - mn1);
                    sacc[mt][nt][0] = p0; sacc[mt][nt][1] = p1;
                    sacc[mt][nt][2] = p2; sacc[mt][nt][3] = p3;
                    rs0 += p0 + p1; rs1 += p2 + p3;
                }
                rs0 += __shfl_xor_sync(0xffffffffu, rs0, 1);
                rs0 += __shfl_xor_sync(0xffffffffu, rs0, 2);
                rs1 += __shfl_xor_sync(0xffffffffu, rs1, 1);
                rs1 += __shfl_xor_sync(0xffffffffu, rs1, 2);
                ll[mt * 2 + 0] = ll[mt * 2 + 0] * al0 + rs0;
                ll[mt * 2 + 1] = ll[mt * 2 + 1] * al1 + rs1;
                #pragma unroll
                for (int nt = 0; nt < 8; nt++) {
                    oacc[mt][nt][0] *= al0; oacc[mt][nt][1] *= al0;
                    oacc[mt][nt][2] *= al1; oacc[mt][nt][3] *= al1;
                }
            }

            // O += P V  (P split hi/lo; V split hi/lo; 3-term)
            #pragma unroll
            for (int ks2 = 0; ks2 < 4; ks2++) {
                uint32_t aP[2][4], aPl[2][4];
                #pragma unroll
                for (int mt = 0; mt < 2; mt++) {
                    #pragma unroll
                    for (int half = 0; half < 2; half++) {
                        const int nt = 2 * ks2 + half;
                        __nv_bfloat16 h00 = __float2bfloat16(sacc[mt][nt][0]);
                        __nv_bfloat16 h01 = __float2bfloat16(sacc[mt][nt][1]);
                        __nv_bfloat16 h10 = __float2bfloat16(sacc[mt][nt][2]);
                        __nv_bfloat16 h11 = __float2bfloat16(sacc[mt][nt][3]);
                        aP[mt][half * 2 + 0] = packbf(h00, h01);
                        aP[mt][half * 2 + 1] = packbf(h10, h11);
                        __nv_bfloat16 e00 = __float2bfloat16(sacc[mt][nt][0] - __bfloat162float(h00));
                        __nv_bfloat16 e01 = __float2bfloat16(sacc[mt][nt][1] - __bfloat162float(h01));
                        __nv_bfloat16 e10 = __float2bfloat16(sacc[mt][nt][2] - __bfloat162float(h10));
                        __nv_bfloat16 e11 = __float2bfloat16(sacc[mt][nt][3] - __bfloat162float(h11));
                        aPl[mt][half * 2 + 0] = packbf(e00, e01);
                        aPl[mt][half * 2 + 1] = packbf(e10, e11);
                    }
                }
                #pragma unroll
                for (int nt16 = 0; nt16 < 4; nt16++) {
                    const uint32_t voff =
                        swz128(ks2 * 16 + vb_row, nt16 * 2 + vb_ch);
                    uint32_t vH[4], vL[4];
                    ldsm4t(vH, bVH + voff);
                    ldsm4t(vL, bVL + voff);
                    #pragma unroll
                    for (int mt = 0; mt < 2; mt++) {
                        #pragma unroll
                        for (int i2 = 0; i2 < 2; i2++) {
                            float* c = oacc[mt][nt16 * 2 + i2];
                            mma16816(c, aP[mt], &vH[i2 * 2]);
                            mma16816(c, aP[mt], &vL[i2 * 2]);
                            mma16816(c, aPl[mt], &vH[i2 * 2]);
                        }
                    }
                }
            }
        }
        __syncthreads();
    }

    // Epilogue: normalize, write bf16 hi/lo into g_oh/g_ol [B,S,D]
    const int b = bh >> 4, h = bh & 15;
    #pragma unroll
    for (int mt = 0; mt < 2; mt++) {
        const float inv0 = 1.f / ll[mt * 2 + 0];
        const float inv1 = 1.f / ll[mt * 2 + 1];
        const int row0 = q0 + wid * 32 + mt * 16 + g;
        #pragma unroll
        for (int nt = 0; nt < 8; nt++) {
            const int col = h * HD + nt * 8 + t2;
            #pragma unroll
            for (int rh = 0; rh < 2; rh++) {
                const float inv = rh ? inv1 : inv0;
                const int row = row0 + rh * 8;
                float vx = oacc[mt][nt][rh * 2 + 0] * inv;
                float vy = oacc[mt][nt][rh * 2 + 1] * inv;
                __nv_bfloat16 hx = __float2bfloat16(vx);
                __nv_bfloat16 hy = __float2bfloat16(vy);
                __nv_bfloat16 lx = __float2bfloat16(vx - __bfloat162float(hx));
                __nv_bfloat16 ly = __float2bfloat16(vy - __bfloat162float(hy));
                size_t idx = (size_t)(b * Ss + row) * Dd + col;
                *(__nv_bfloat162*)&g_oh[idx] = __halves2bfloat162(hx, hy);
                *(__nv_bfloat162*)&g_ol[idx] = __halves2bfloat162(lx, ly);
            }
        }
    }
}

// ---------------------------------------------------------------------------
// Launch — only harness pointers cross the host/device boundary
// ---------------------------------------------------------------------------
extern "C" void kernel_launch(void* const* d_in, const int* in_sizes, int n_in,
                              void* d_out, int out_size)
{
    const float* x  = (const float*)d_in[0];
    const float* Wq = (const float*)d_in[1];
    const float* bq = (const float*)d_in[2];
    const float* Wk = (const float*)d_in[3];
    const float* bk = (const float*)d_in[4];
    const float* Wv = (const float*)d_in[5];
    const float* bv = (const float*)d_in[6];
    const float* Wp = (const float*)d_in[7];
    const float* bp = (const float*)d_in[8];
    float* out = (float*)d_out;

    cudaFuncSetAttribute(gemm_bf16x3<0>,
                         cudaFuncAttributeMaxDynamicSharedMemorySize, GEMM_SMEM);
    cudaFuncSetAttribute(gemm_bf16x3<1>,
                         cudaFuncAttributeMaxDynamicSharedMemorySize, GEMM_SMEM);
    cudaFuncSetAttribute(attn_mma,
                         cudaFuncAttributeMaxDynamicSharedMemorySize, ATT_SMEM);

    // Conversions
    const int n4 = Mtot * Dd / 4;
    k_conv_x<<<(n4 + 255) / 256, 256>>>(x, n4);
    k_conv_wqkv<<<dim3(16, 16, 3), 256>>>(Wq, Wk, Wv);
    k_conv_wp<<<dim3(16, 16), 256>>>(Wp);
    k_bias<<<12, 256>>>(bq, bk, bv);

    // QKV projection (q/k/v all written hi/lo into [B,H,S,HD])
    gemm_bf16x3<1><<<dim3(24, 64), 128, GEMM_SMEM>>>(nullptr, nullptr);

    // Attention (mma.sync, split precision, 4 warps x 32 rows)
    attn_mma<<<dim3(16, 64), 128, ATT_SMEM>>>();

    // Output projection
    gemm_bf16x3<0><<<dim3(8, 64), 128, GEMM_SMEM>>>(bp, out);
}